// round 2
// baseline (speedup 1.0000x reference)
#include <cuda_runtime.h>
#include <math.h>

#define N_NODES 20000
#define N_EDGES 320000
#define NPB 8

// ---------------- device scratch ----------------
__device__ float g_xA[N_NODES*13*32];
__device__ float g_xB[N_NODES*13*32];
__device__ float g_h [N_NODES*12*32];
__device__ float g_acc[N_NODES*12*32];
__device__ float g_pA[N_NODES*12*32];
__device__ float g_pB[N_NODES*12*32];
__device__ float g_skip[N_NODES*256];
__device__ int    g_rowptr[N_NODES+1];
__device__ int    g_curs[N_NODES];
__device__ int    g_cnt[N_NODES];
__device__ float  g_invdeg[N_NODES];
__device__ int    g_col[N_EDGES];
__device__ double g_stats[64];   // [0:32) sum, [32:64) sumsq
__device__ float  g_affine[64];  // [0:32) scale, [32:64) bias

// ---------------- init ----------------
__global__ void k_init(){
    int i = blockIdx.x*256 + threadIdx.x;      // covers N_NODES*256 = skip size
    g_skip[i] = 0.f;
    if(i < N_NODES) g_cnt[i] = 0;
    if(i < 64){ g_stats[i] = 0.0; g_affine[i] = (i < 32) ? 1.f : 0.f; }
}

__global__ void k_hist(const int* __restrict__ dst){
    int e = blockIdx.x*256 + threadIdx.x;
    if(e < N_EDGES) atomicAdd(&g_cnt[dst[e]], 1);
}

__global__ void k_scan(){
    __shared__ int sh[1024];
    __shared__ int carry;
    int tid = threadIdx.x;
    if(tid == 0){ carry = 0; g_rowptr[0] = 0; }
    __syncthreads();
    for(int base = 0; base < N_NODES; base += 1024){
        int i = base + tid;
        int v = (i < N_NODES) ? g_cnt[i] : 0;
        sh[tid] = v;
        __syncthreads();
        for(int off = 1; off < 1024; off <<= 1){
            int tv = (tid >= off) ? sh[tid-off] : 0;
            __syncthreads();
            sh[tid] += tv;
            __syncthreads();
        }
        if(i < N_NODES){
            g_rowptr[i+1] = sh[tid] + carry;
            g_curs[i]     = sh[tid] - v + carry;   // exclusive
        }
        __syncthreads();
        if(tid == 0) carry += sh[1023];
        __syncthreads();
    }
}

__global__ void k_deg(){
    int n = blockIdx.x*256 + threadIdx.x;
    if(n < N_NODES){ int c = g_cnt[n]; g_invdeg[n] = 1.f/(float)(c > 0 ? c : 1); }
}

__global__ void k_fill(const int* __restrict__ src, const int* __restrict__ dst){
    int e = blockIdx.x*256 + threadIdx.x;
    if(e < N_EDGES){
        int pos = atomicAdd(&g_curs[dst[e]], 1);
        g_col[pos] = src[e];
    }
}

// ---------------- enter 1x1 conv:  x0[n][t][c] ----------------
__global__ void k_enter(const float* __restrict__ inp,
                        const float* __restrict__ w, const float* __restrict__ b){
    int idx = blockIdx.x*256 + threadIdx.x;
    if(idx >= N_NODES*13*32) return;
    int o  = idx & 31;
    int nt = idx >> 5;
    const float* ip = inp + nt*3;
    g_xA[idx] = b[o] + w[o*3+0]*ip[0] + w[o*3+1]*ip[1] + w[o*3+2]*ip[2];
}

// ---------------- gated dilated conv + h@W0 + skip(last col) ----------------
// block (32, NPB): x = out channel, y = node-in-block
template<int TIN, int D, bool LAST>
__global__ void __launch_bounds__(32*NPB) k_conv(
    const float* __restrict__ xin,
    const float* __restrict__ fw_g, const float* __restrict__ fb_g,
    const float* __restrict__ gw_g, const float* __restrict__ gb_g,
    const float* __restrict__ w0_g,
    const float* __restrict__ sw_g, const float* __restrict__ sb_g)
{
    constexpr int TOUT = TIN - D;
    extern __shared__ float sm[];
    float* fw  = sm;                                 // [i][k][o]  2048
    float* gw  = sm + 2048;                          // 2048
    float* w0  = sm + 4096;                          // [c][o] 1024 (absent if LAST)
    float* swT = sm + 4096 + (LAST ? 0 : 1024);      // [c][O] 8192
    float* xs  = swT + 8192;                         // NPB*TIN*32

    int tx = threadIdx.x, ty = threadIdx.y;
    int tid = ty*32 + tx;
    for(int j = tid; j < 2048; j += 32*NPB){
        int o = j & 31, k = (j>>5) & 1, i = j>>6;
        fw[j] = fw_g[(o*32+i)*2+k];
        gw[j] = gw_g[(o*32+i)*2+k];
    }
    if(!LAST) for(int j = tid; j < 1024; j += 32*NPB) w0[j] = w0_g[j];
    for(int j = tid; j < 8192; j += 32*NPB){ int O = j & 255, c = j >> 8; swT[j] = sw_g[O*32+c]; }

    int n = blockIdx.x*NPB + ty;
    float scl = g_affine[tx], bia = g_affine[32+tx];
    const float* xp = xin + n*(TIN*32);
    float* xrow = xs + ty*(TIN*32);
    for(int idx = tx; idx < TIN*32; idx += 32)
        xrow[idx] = xp[idx]*scl + bia;               // (idx&31)==tx
    __syncthreads();

    float f[TOUT], g[TOUT];
    float fb = fb_g[tx], gb = gb_g[tx];
#pragma unroll
    for(int t = 0; t < TOUT; t++){ f[t] = fb; g[t] = gb; }
#pragma unroll
    for(int i = 0; i < 32; i++){
        float wf0 = fw[i*64+tx],    wf1 = fw[i*64+32+tx];
        float wg0 = gw[i*64+tx],    wg1 = gw[i*64+32+tx];
#pragma unroll
        for(int t = 0; t < TOUT; t++){
            float x0 = xrow[t*32+i], x1 = xrow[(t+D)*32+i];
            f[t] += wf0*x0; f[t] += wf1*x1;
            g[t] += wg0*x0; g[t] += wg1*x1;
        }
    }
    __syncthreads();                                  // done reading xs
    float* hrow = xs + ty*(TOUT*32);                  // reuse xs region
#pragma unroll
    for(int t = 0; t < TOUT; t++){
        float hv = tanhf(f[t]) * (1.f/(1.f + expf(-g[t])));
        hrow[t*32+tx] = hv;
        if(!LAST) g_h[(n*TOUT + t)*32 + tx] = hv;
    }
    __syncthreads();

    if(!LAST){
        float u[TOUT];
#pragma unroll
        for(int t = 0; t < TOUT; t++) u[t] = 0.f;
#pragma unroll
        for(int c = 0; c < 32; c++){
            float w = w0[c*32+tx];
#pragma unroll
            for(int t = 0; t < TOUT; t++) u[t] += hrow[t*32+c]*w;
        }
#pragma unroll
        for(int t = 0; t < TOUT; t++) g_acc[(n*TOUT + t)*32 + tx] = u[t];
    }

    // skip projection — only the last time column survives truncation
    const float* hl = hrow + (TOUT-1)*32;
    float* sk = g_skip + n*256;
#pragma unroll
    for(int j = 0; j < 8; j++){
        int O = tx + j*32;
        float a = sb_g[O];
#pragma unroll
        for(int c = 0; c < 32; c++) a += hl[c]*swT[c*256+O];
        sk[O] += a;
    }
}

// ---------------- one diffusion hop:  cur_out = A*in ; acc += cur_out @ Wk ----------------
// block (8,32): x = channel quad (0..7), y = pair-in-block (0..31). pair p = n*t + tt
__global__ void __launch_bounds__(256) k_prop(
    const float* __restrict__ in, float* __restrict__ curout,
    float* __restrict__ acc, const float* __restrict__ Wk,
    int t, int P, int writeCur)
{
    __shared__ __align__(16) float sh[32*40];
    __shared__ __align__(16) float Ws[1024];
    int tx = threadIdx.x, ty = threadIdx.y;
    int tid = ty*8 + tx;
    for(int j = tid; j < 1024; j += 256) Ws[j] = Wk[j];

    int p = blockIdx.x*32 + ty;
    float4 s = make_float4(0.f,0.f,0.f,0.f);
    if(p < P){
        int n  = p / t;
        int tt = p - n*t;
        int beg = g_rowptr[n], end = g_rowptr[n+1];
        const float4* in4 = (const float4*)in;
        for(int e = beg; e < end; e++){
            int src = g_col[e];
            float4 v = in4[(src*t + tt)*8 + tx];
            s.x += v.x; s.y += v.y; s.z += v.z; s.w += v.w;
        }
        float iv = g_invdeg[n];
        s.x *= iv; s.y *= iv; s.z *= iv; s.w *= iv;
        if(writeCur) ((float4*)curout)[p*8 + tx] = s;
    }
    ((float4*)(sh + ty*40))[tx] = s;
    __syncthreads();
    if(p < P){
        float4 a = make_float4(0.f,0.f,0.f,0.f);
#pragma unroll
        for(int c = 0; c < 32; c++){
            float hv = sh[ty*40 + c];
            float4 w = ((const float4*)(Ws + c*32))[tx];
            a.x += hv*w.x; a.y += hv*w.y; a.z += hv*w.z; a.w += hv*w.w;
        }
        float4* ap = (float4*)acc + p*8 + tx;
        float4 old = *ap;
        old.x += a.x; old.y += a.y; old.z += a.z; old.w += a.w;
        *ap = old;
    }
}

// ---------------- finalize layer: x_new_pre = acc + gc_b + affine(x_old) ; BN stats ----------------
__global__ void __launch_bounds__(256) k_fin(
    const float* __restrict__ xold, float* __restrict__ xnew,
    const float* __restrict__ gcb, int t, int tin, int P)
{
    int tx = threadIdx.x, ty = threadIdx.y;        // (32, 8)
    float scl = g_affine[tx], bia = g_affine[32+tx];
    float gb = gcb[tx];
    int off = tin - t;
    float sum = 0.f, sq = 0.f;
    for(int p = blockIdx.x*8 + ty; p < P; p += gridDim.x*8){
        int n = p / t, tt = p - n*t;
        float v = g_acc[p*32+tx] + gb + xold[(n*tin + tt + off)*32 + tx]*scl + bia;
        xnew[p*32+tx] = v;
        sum += v; sq += v*v;
    }
    __shared__ float rs[8][32], rq[8][32];
    rs[ty][tx] = sum; rq[ty][tx] = sq;
    __syncthreads();
    if(ty == 0){
        float a = 0.f, b = 0.f;
#pragma unroll
        for(int j = 0; j < 8; j++){ a += rs[j][tx]; b += rq[j][tx]; }
        atomicAdd(&g_stats[tx],    (double)a);
        atomicAdd(&g_stats[32+tx], (double)b);
    }
}

__global__ void k_affine(const float* __restrict__ bng, const float* __restrict__ bnb, float invCnt){
    int c = threadIdx.x;   // 32 threads
    double mu  = g_stats[c]    * (double)invCnt;
    double var = g_stats[32+c] * (double)invCnt - mu*mu;
    if(var < 0.0) var = 0.0;
    float scale = bng[c] * rsqrtf((float)var + 1e-5f);
    g_affine[c]    = scale;
    g_affine[32+c] = bnb[c] - (float)mu*scale;
    g_stats[c] = 0.0; g_stats[32+c] = 0.0;
}

// ---------------- head: relu(skip) -> relu(W1+b1) -> W2+b2 ----------------
// block 128 threads, 16 nodes
__global__ void __launch_bounds__(128) k_head(
    const float* __restrict__ w1, const float* __restrict__ b1,
    const float* __restrict__ w2, const float* __restrict__ b2,
    float* __restrict__ out)
{
    extern __shared__ float sm[];
    float* y1s = sm;                 // 16*512
    float* buf = sm + 16*512;        // max(16*256, 24*512) = 12288
    int tid = threadIdx.x;
    int n0 = blockIdx.x*16;

    for(int j = tid; j < 16*256; j += 128)
        buf[j] = fmaxf(g_skip[n0*256 + j], 0.f);
    __syncthreads();

    const float4* buf4 = (const float4*)buf;
    for(int oo = 0; oo < 4; oo++){
        int o = tid + oo*128;
        float acc[16];
#pragma unroll
        for(int m = 0; m < 16; m++) acc[m] = 0.f;
        const float4* wr = (const float4*)(w1 + o*256);
        for(int c4 = 0; c4 < 64; c4++){
            float4 w = wr[c4];
#pragma unroll
            for(int m = 0; m < 16; m++){
                float4 s = buf4[m*64 + c4];
                acc[m] += w.x*s.x + w.y*s.y + w.z*s.z + w.w*s.w;
            }
        }
        float bb = b1[o];
#pragma unroll
        for(int m = 0; m < 16; m++) y1s[m*512 + o] = fmaxf(acc[m] + bb, 0.f);
    }
    __syncthreads();
    for(int j = tid; j < 24*512; j += 128) buf[j] = w2[j];
    __syncthreads();

    const float4* y1s4 = (const float4*)y1s;
    for(int a = tid; a < 16*24; a += 128){
        int m = a / 24, o = a - m*24;
        float acc = b2[o];
        const float4* wp = (const float4*)(buf + o*512);
        const float4* yp = y1s4 + m*128;
        for(int c4 = 0; c4 < 128; c4++){
            float4 ww = wp[c4], yy = yp[c4];
            acc += ww.x*yy.x + ww.y*yy.y + ww.z*yy.z + ww.w*yy.w;
        }
        out[(n0 + m)*24 + o] = acc;
    }
}

// ---------------- host ----------------
static inline size_t conv_smem(int tin, bool last){
    return (size_t)(2048 + 2048 + (last ? 0 : 1024) + 8192 + NPB*tin*32) * 4;
}

extern "C" void kernel_launch(void* const* d_in, const int* in_sizes, int n_in,
                              void* d_out, int out_size)
{
    const float* inputs  = (const float*)d_in[0];
    const int*   esrc    = (const int*)  d_in[1];
    const int*   edst    = (const int*)  d_in[2];
    const float* enter_w = (const float*)d_in[3];
    const float* enter_b = (const float*)d_in[4];
    const float* filt_w  = (const float*)d_in[5];
    const float* filt_b  = (const float*)d_in[6];
    const float* gate_w  = (const float*)d_in[7];
    const float* gate_b  = (const float*)d_in[8];
    const float* gc_w    = (const float*)d_in[9];
    const float* gc_b    = (const float*)d_in[10];
    const float* skip_w  = (const float*)d_in[11];
    const float* skip_b  = (const float*)d_in[12];
    const float* bn_g    = (const float*)d_in[13];
    const float* bn_b    = (const float*)d_in[14];
    const float* out1_w  = (const float*)d_in[15];
    const float* out1_b  = (const float*)d_in[16];
    const float* out2_w  = (const float*)d_in[17];
    const float* out2_b  = (const float*)d_in[18];
    float* out = (float*)d_out;

    cudaFuncSetAttribute(k_conv<13,1,false>, cudaFuncAttributeMaxDynamicSharedMemorySize, (int)conv_smem(13,false));
    cudaFuncSetAttribute(k_conv<12,2,false>, cudaFuncAttributeMaxDynamicSharedMemorySize, (int)conv_smem(12,false));
    cudaFuncSetAttribute(k_conv<10,1,false>, cudaFuncAttributeMaxDynamicSharedMemorySize, (int)conv_smem(10,false));
    cudaFuncSetAttribute(k_conv< 9,2,false>, cudaFuncAttributeMaxDynamicSharedMemorySize, (int)conv_smem(9,false));
    cudaFuncSetAttribute(k_conv< 7,1,false>, cudaFuncAttributeMaxDynamicSharedMemorySize, (int)conv_smem(7,false));
    cudaFuncSetAttribute(k_conv< 6,2,false>, cudaFuncAttributeMaxDynamicSharedMemorySize, (int)conv_smem(6,false));
    cudaFuncSetAttribute(k_conv< 4,1,false>, cudaFuncAttributeMaxDynamicSharedMemorySize, (int)conv_smem(4,false));
    cudaFuncSetAttribute(k_conv< 3,2,true >, cudaFuncAttributeMaxDynamicSharedMemorySize, (int)conv_smem(3,true));
    cudaFuncSetAttribute(k_head, cudaFuncAttributeMaxDynamicSharedMemorySize, (16*512 + 24*512)*4);

    float *xA, *xB, *pA, *pB, *hh, *acc;
    cudaGetSymbolAddress((void**)&xA,  g_xA);
    cudaGetSymbolAddress((void**)&xB,  g_xB);
    cudaGetSymbolAddress((void**)&pA,  g_pA);
    cudaGetSymbolAddress((void**)&pB,  g_pB);
    cudaGetSymbolAddress((void**)&hh,  g_h);
    cudaGetSymbolAddress((void**)&acc, g_acc);

    k_init<<<N_NODES, 256>>>();
    k_hist<<<(N_EDGES+255)/256, 256>>>(edst);
    k_scan<<<1, 1024>>>();
    k_deg <<<(N_NODES+255)/256, 256>>>();
    k_fill<<<(N_EDGES+255)/256, 256>>>(esrc, edst);
    k_enter<<<(N_NODES*13*32+255)/256, 256>>>(inputs, enter_w, enter_b);

    dim3 cb(32, NPB);
    dim3 pb(8, 32);
    dim3 fb(32, 8);
    const int grid_conv = N_NODES / NPB;

    // layer table: TIN, D (TOUT = TIN-D)
    // l0:(13,1) l1:(12,2) l2:(10,1) l3:(9,2) l4:(7,1) l5:(6,2) l6:(4,1) l7:(3,2,last)
#define LAYER(l, TIN, DD, XIN, XNEW)                                                            \
    {                                                                                           \
        const int t = (TIN) - (DD);                                                             \
        const int P = N_NODES * t;                                                              \
        k_conv<TIN, DD, false><<<grid_conv, cb, conv_smem(TIN,false)>>>(                        \
            XIN, filt_w + (l)*2048, filt_b + (l)*32, gate_w + (l)*2048, gate_b + (l)*32,        \
            gc_w + (l)*4096, skip_w + (l)*8192, skip_b + (l)*256);                              \
        int pg = (P + 31) / 32;                                                                 \
        k_prop<<<pg, pb>>>(hh, pA, acc, gc_w + ((l)*4 + 1)*1024, t, P, 1);                      \
        k_prop<<<pg, pb>>>(pA, pB, acc, gc_w + ((l)*4 + 2)*1024, t, P, 1);                      \
        k_prop<<<pg, pb>>>(pB, pA, acc, gc_w + ((l)*4 + 3)*1024, t, P, 0);                      \
        k_fin<<<1024, fb>>>(XIN, XNEW, gc_b + (l)*32, t, TIN, P);                               \
        k_affine<<<1, 32>>>(bn_g + (l)*32, bn_b + (l)*32, 1.f/((float)N_NODES * (float)t));     \
    }

    LAYER(0, 13, 1, xA, xB)
    LAYER(1, 12, 2, xB, xA)
    LAYER(2, 10, 1, xA, xB)
    LAYER(3,  9, 2, xB, xA)
    LAYER(4,  7, 1, xA, xB)
    LAYER(5,  6, 2, xB, xA)
    LAYER(6,  4, 1, xA, xB)
#undef LAYER

    // last layer: conv + skip only (graph conv / BN / residual are dead code)
    k_conv<3, 2, true><<<grid_conv, cb, conv_smem(3,true)>>>(
        xB, filt_w + 7*2048, filt_b + 7*32, gate_w + 7*2048, gate_b + 7*32,
        gc_w /*unused*/, skip_w + 7*8192, skip_b + 7*256);

    k_head<<<N_NODES/16, 128, (16*512 + 24*512)*4>>>(out1_w, out1_b, out2_w, out2_b, out);
}

// round 3
// speedup vs baseline: 1.1666x; 1.1666x over previous
#include <cuda_runtime.h>
#include <math.h>

#define N_NODES 20000
#define N_EDGES 320000
#define NPB 8

// ---------------- device scratch ----------------
__device__ float  g_xA[N_NODES*13*32];
__device__ float  g_xB[N_NODES*13*32];
__device__ float  g_h [N_NODES*12*32];
__device__ float  g_acc[N_NODES*12*32];
__device__ float  g_pA[N_NODES*12*32];
__device__ float  g_pB[N_NODES*12*32];
__device__ float  g_hl[8*N_NODES*32];
__device__ int    g_rowptr[N_NODES+1];
__device__ int    g_curs[N_NODES];
__device__ int    g_cnt[N_NODES];          // static zero-init; k_deg re-zeroes after use
__device__ float  g_invdeg[N_NODES];
__device__ int    g_col[N_EDGES];
__device__ double g_statsS[32*64];         // 32 shards x (32 sum, 32 sumsq); zeroed in finalize
__device__ float  g_affine[64];            // scale[32], bias[32]
__device__ int    g_done;                  // finalize counter; reset in finalize

// ---------------- setup ----------------
__global__ void k_hist(const int* __restrict__ dst){
    int i = blockIdx.x*256 + threadIdx.x;
    if(i < 64) g_affine[i] = (i < 32) ? 1.f : 0.f;   // identity affine for layer 0
    if(i < N_EDGES) atomicAdd(&g_cnt[dst[i]], 1);
}

__global__ void k_scan(){            // 1 block, 1024 threads; chunk-per-thread + shuffle scan
    const int CH = 20;               // 1024*20 = 20480 >= N_NODES
    int tid = threadIdx.x;
    int b0 = tid*CH; if(b0 > N_NODES) b0 = N_NODES;
    int b1 = b0 + CH; if(b1 > N_NODES) b1 = N_NODES;
    int sum = 0;
    for(int i = b0; i < b1; i++) sum += g_cnt[i];
    int lane = tid & 31, w = tid >> 5;
    int v = sum;
#pragma unroll
    for(int o = 1; o < 32; o <<= 1){
        int t = __shfl_up_sync(0xffffffffu, v, o);
        if(lane >= o) v += t;
    }
    __shared__ int wsum[32];
    if(lane == 31) wsum[w] = v;
    __syncthreads();
    if(w == 0){
        int x = wsum[lane];
#pragma unroll
        for(int o = 1; o < 32; o <<= 1){
            int t = __shfl_up_sync(0xffffffffu, x, o);
            if(lane >= o) x += t;
        }
        wsum[lane] = x;
    }
    __syncthreads();
    int pre = v - sum + ((w > 0) ? wsum[w-1] : 0);   // exclusive prefix for this thread
    int run = pre;
    for(int i = b0; i < b1; i++){
        int c = g_cnt[i];
        g_curs[i] = run;
        run += c;
        g_rowptr[i+1] = run;
    }
    if(tid == 0) g_rowptr[0] = 0;
}

__global__ void k_deg(){
    int n = blockIdx.x*256 + threadIdx.x;
    if(n < N_NODES){
        int c = g_cnt[n];
        g_invdeg[n] = 1.f/(float)(c > 0 ? c : 1);
        g_cnt[n] = 0;                 // reset for next replay
    }
}

__global__ void k_fill(const int* __restrict__ src, const int* __restrict__ dst){
    int e = blockIdx.x*256 + threadIdx.x;
    if(e < N_EDGES){
        int pos = atomicAdd(&g_curs[dst[e]], 1);
        g_col[pos] = src[e];
    }
}

// ---------------- gated dilated conv (+enter fusion) + h@W0 + hl ----------------
// block (32, NPB): x = channel, y = node-in-block
template<int TIN, int D, bool ENTER, bool LAST>
__global__ void __launch_bounds__(32*NPB) k_conv(
    const float* __restrict__ xin,
    const float* __restrict__ ew, const float* __restrict__ eb,
    const float* __restrict__ fw_g, const float* __restrict__ fb_g,
    const float* __restrict__ gw_g, const float* __restrict__ gb_g,
    const float* __restrict__ w0_g,
    float* __restrict__ hl_out, float* __restrict__ xsave)
{
    constexpr int TOUT = TIN - D;
    extern __shared__ float sm[];
    float* fw  = sm;                                   // [i][k][o] 2048
    float* gw  = sm + 2048;                            // 2048
    float* w0  = sm + 4096;                            // 1024 (if !LAST)
    float* ews = sm + 4096 + (LAST ? 0 : 1024);        // 128 (if ENTER)
    float* xs  = ews + (ENTER ? 128 : 0);              // NPB*TIN*32

    int tx = threadIdx.x, ty = threadIdx.y;
    int tid = ty*32 + tx;
    for(int j = tid; j < 2048; j += 32*NPB){
        int o = j & 31, k = (j>>5) & 1, i = j>>6;
        fw[j] = fw_g[(o*32+i)*2+k];
        gw[j] = gw_g[(o*32+i)*2+k];
    }
    if(!LAST) for(int j = tid; j < 1024; j += 32*NPB) w0[j] = w0_g[j];
    if(ENTER){
        if(tid < 96) ews[tid] = ew[tid];
        if(tid < 32) ews[96+tid] = eb[tid];
    }
    __syncthreads();

    int n = blockIdx.x*NPB + ty;
    float* xrow = xs + ty*(TIN*32);
    if(ENTER){
        const float* ip = xin + n*(TIN*3);
        float we0 = ews[tx*3+0], we1 = ews[tx*3+1], we2 = ews[tx*3+2], be = ews[96+tx];
#pragma unroll
        for(int tt = 0; tt < TIN; tt++){
            float v = be + we0*ip[tt*3+0] + we1*ip[tt*3+1] + we2*ip[tt*3+2];
            xrow[tt*32+tx] = v;
            xsave[(n*TIN+tt)*32+tx] = v;     // residual source for propfin
        }
    } else {
        float scl = g_affine[tx], bia = g_affine[32+tx];
        const float* xp = xin + n*(TIN*32);
        for(int idx = tx; idx < TIN*32; idx += 32)
            xrow[idx] = xp[idx]*scl + bia;
    }
    __syncwarp();

    float f[TOUT], g[TOUT];
    float fb = fb_g[tx], gb = gb_g[tx];
#pragma unroll
    for(int t = 0; t < TOUT; t++){ f[t] = fb; g[t] = gb; }
#pragma unroll
    for(int i = 0; i < 32; i++){
        float wf0 = fw[i*64+tx], wf1 = fw[i*64+32+tx];
        float wg0 = gw[i*64+tx], wg1 = gw[i*64+32+tx];
#pragma unroll
        for(int tt = 0; tt < TIN; tt++){
            float xv = xrow[tt*32+i];
            if(tt < TOUT){ f[tt]    += wf0*xv; g[tt]    += wg0*xv; }
            if(tt >= D)  { f[tt-D]  += wf1*xv; g[tt-D]  += wg1*xv; }
        }
    }
    __syncwarp();                      // warpmates done reading xrow

    if(!LAST){
        float* hrow = xrow;            // reuse own row (first TOUT*32 of it)
#pragma unroll
        for(int t = 0; t < TOUT; t++){
            float h = tanhf(f[t]) * (1.f/(1.f + expf(-g[t])));
            hrow[t*32+tx] = h;
            g_h[(n*TOUT+t)*32+tx] = h;
        }
        __syncwarp();
        hl_out[n*32+tx] = hrow[(TOUT-1)*32+tx];

        float w0r[32];
#pragma unroll
        for(int c = 0; c < 32; c++) w0r[c] = w0[c*32+tx];
        float u[TOUT];
#pragma unroll
        for(int t = 0; t < TOUT; t++) u[t] = 0.f;
        const float4* hp4 = (const float4*)hrow;
#pragma unroll
        for(int c4 = 0; c4 < 8; c4++){
#pragma unroll
            for(int t = 0; t < TOUT; t++){
                float4 hh = hp4[t*8+c4];
                u[t] += hh.x*w0r[c4*4+0] + hh.y*w0r[c4*4+1] + hh.z*w0r[c4*4+2] + hh.w*w0r[c4*4+3];
            }
        }
#pragma unroll
        for(int t = 0; t < TOUT; t++) g_acc[(n*TOUT+t)*32+tx] = u[t];
    } else {
        float h = tanhf(f[TOUT-1]) * (1.f/(1.f + expf(-g[TOUT-1])));
        hl_out[n*32+tx] = h;
    }
}

// ---------------- diffusion hop: cur = A*in ; g_acc += cur @ Wk ----------------
// one warp per node; lane = channel
template<int T>
__global__ void __launch_bounds__(32*NPB) k_prop(
    const float* __restrict__ in, float* __restrict__ curout,
    const float* __restrict__ Wk)
{
    __shared__ float Ws[1024];
    __shared__ __align__(16) float smS[NPB*12*32];
    int tid = threadIdx.x, lane = tid & 31, wid = tid >> 5;
    for(int j = tid; j < 1024; j += 32*NPB) Ws[j] = Wk[j];
    __syncthreads();
    float Wreg[32];
#pragma unroll
    for(int c = 0; c < 32; c++) Wreg[c] = Ws[c*32+lane];

    int n = blockIdx.x*NPB + wid;
    int beg = g_rowptr[n], end = g_rowptr[n+1];
    float s[T];
#pragma unroll
    for(int t = 0; t < T; t++) s[t] = 0.f;
    for(int e = beg; e < end; e += 32){
        int m = end - e; if(m > 32) m = 32;
        int col = (lane < m) ? g_col[e+lane] : 0;
        for(int j = 0; j < m; j++){
            int src = __shfl_sync(0xffffffffu, col, j);
            const float* r = in + src*(T*32) + lane;
#pragma unroll
            for(int t = 0; t < T; t++) s[t] += r[t*32];
        }
    }
    float iv = g_invdeg[n];
#pragma unroll
    for(int t = 0; t < T; t++) s[t] *= iv;
    {
        float* cp = curout + n*(T*32) + lane;
#pragma unroll
        for(int t = 0; t < T; t++) cp[t*32] = s[t];
    }
    float* tile = smS + wid*(T*32);
#pragma unroll
    for(int t = 0; t < T; t++) tile[t*32+lane] = s[t];
    __syncwarp();
    float a[T];
#pragma unroll
    for(int t = 0; t < T; t++) a[t] = 0.f;
    const float4* tp = (const float4*)tile;
#pragma unroll
    for(int c4 = 0; c4 < 8; c4++){
#pragma unroll
        for(int t = 0; t < T; t++){
            float4 sv = tp[t*8+c4];
            a[t] += sv.x*Wreg[c4*4+0] + sv.y*Wreg[c4*4+1] + sv.z*Wreg[c4*4+2] + sv.w*Wreg[c4*4+3];
        }
    }
    float* ap = g_acc + n*(T*32) + lane;
#pragma unroll
    for(int t = 0; t < T; t++) ap[t*32] += a[t];
}

// ---------------- hop 3 fused with finalize: xnew = A*in@Wk + acc + gcb + affine(xold); BN stats ----------------
template<int T, int TIN>
__global__ void __launch_bounds__(32*NPB) k_propfin(
    const float* __restrict__ in, const float* __restrict__ Wk,
    const float* __restrict__ xold, float* __restrict__ xnew,
    const float* __restrict__ gcb,
    const float* __restrict__ bng, const float* __restrict__ bnb, float invCnt)
{
    __shared__ float Ws[1024];
    __shared__ __align__(16) float smS[NPB*12*32];
    __shared__ float rs[32*NPB], rq[32*NPB];
    __shared__ int isLast;
    int tid = threadIdx.x, lane = tid & 31, wid = tid >> 5;
    for(int j = tid; j < 1024; j += 32*NPB) Ws[j] = Wk[j];
    __syncthreads();
    float Wreg[32];
#pragma unroll
    for(int c = 0; c < 32; c++) Wreg[c] = Ws[c*32+lane];

    int n = blockIdx.x*NPB + wid;
    int beg = g_rowptr[n], end = g_rowptr[n+1];
    float s[T];
#pragma unroll
    for(int t = 0; t < T; t++) s[t] = 0.f;
    for(int e = beg; e < end; e += 32){
        int m = end - e; if(m > 32) m = 32;
        int col = (lane < m) ? g_col[e+lane] : 0;
        for(int j = 0; j < m; j++){
            int src = __shfl_sync(0xffffffffu, col, j);
            const float* r = in + src*(T*32) + lane;
#pragma unroll
            for(int t = 0; t < T; t++) s[t] += r[t*32];
        }
    }
    float iv = g_invdeg[n];
#pragma unroll
    for(int t = 0; t < T; t++) s[t] *= iv;
    float* tile = smS + wid*(T*32);
#pragma unroll
    for(int t = 0; t < T; t++) tile[t*32+lane] = s[t];
    __syncwarp();
    float a[T];
#pragma unroll
    for(int t = 0; t < T; t++) a[t] = 0.f;
    const float4* tp = (const float4*)tile;
#pragma unroll
    for(int c4 = 0; c4 < 8; c4++){
#pragma unroll
        for(int t = 0; t < T; t++){
            float4 sv = tp[t*8+c4];
            a[t] += sv.x*Wreg[c4*4+0] + sv.y*Wreg[c4*4+1] + sv.z*Wreg[c4*4+2] + sv.w*Wreg[c4*4+3];
        }
    }
    float scl = g_affine[lane], bia = g_affine[32+lane];
    float gb  = gcb[lane];
    const float* ao = g_acc + n*(T*32) + lane;
    const float* xo = xold + (n*TIN + (TIN-T))*32 + lane;
    float* xn = xnew + n*(T*32) + lane;
    float sum = 0.f, sq = 0.f;
#pragma unroll
    for(int t = 0; t < T; t++){
        float v = a[t] + ao[t*32] + gb + xo[t*32]*scl + bia;
        xn[t*32] = v;
        sum += v; sq += v*v;
    }
    rs[tid] = sum; rq[tid] = sq;
    __syncthreads();
    if(tid < 32){
        float ts = 0.f, tq = 0.f;
#pragma unroll
        for(int w = 0; w < NPB; w++){ ts += rs[w*32+tid]; tq += rq[w*32+tid]; }
        int sh = (blockIdx.x & 31)*64;
        atomicAdd(&g_statsS[sh+tid],    (double)ts);
        atomicAdd(&g_statsS[sh+32+tid], (double)tq);
    }
    if(tid == 0){
        __threadfence();
        int d = atomicAdd(&g_done, 1);
        isLast = (d == (int)gridDim.x - 1) ? 1 : 0;
    }
    __syncthreads();
    if(isLast){
        __threadfence();
        if(tid < 32){
            double S = 0.0, Q = 0.0;
            for(int k = 0; k < 32; k++){ S += g_statsS[k*64+tid]; Q += g_statsS[k*64+32+tid]; }
            double mu  = S*(double)invCnt;
            double var = Q*(double)invCnt - mu*mu;
            if(var < 0.0) var = 0.0;
            float scale = bng[tid] * rsqrtf((float)var + 1e-5f);
            g_affine[tid]    = scale;
            g_affine[32+tid] = bnb[tid] - (float)mu*scale;
        }
        __syncthreads();
        for(int j = tid; j < 2048; j += 32*NPB) g_statsS[j] = 0.0;
        if(tid == 0) g_done = 0;
    }
}

// ---------------- head: skip = sum_l hl_l @ swT_l + sum_l sb_l ; relu ; out1 ; relu ; out2 ----------------
// 256 threads, 16 nodes/block
__global__ void __launch_bounds__(256) k_head(
    const float* __restrict__ sw_g, const float* __restrict__ sb_g,
    const float* __restrict__ w1, const float* __restrict__ b1,
    const float* __restrict__ w2, const float* __restrict__ b2,
    float* __restrict__ out)
{
    extern __shared__ float sm[];
    float* hlsT    = sm;            // [(l*32+c)*20 + m], 5120
    float* skipacc = sm + 5120;     // [m*256 + O], 4096
    float* wbuf    = sm + 9216;     // [c*257 + O], 8224
    float* y1s     = sm + 17440;    // [m*512 + o], 8192
    int tid = threadIdx.x;
    int n0 = blockIdx.x*16;

    for(int j = tid; j < 8*16*32; j += 256){
        int c = j & 31, m = (j>>5) & 15, l = j>>9;
        hlsT[(l*32+c)*20 + m] = g_hl[l*(N_NODES*32) + (n0+m)*32 + c];
    }
    float a[16];
    {
        float bs = 0.f;
        for(int l = 0; l < 8; l++) bs += sb_g[l*256+tid];
#pragma unroll
        for(int m = 0; m < 16; m++) a[m] = bs;
    }
    for(int l = 0; l < 8; l++){
        __syncthreads();
        for(int j = tid; j < 8192; j += 256){
            int c = j & 31, O = j >> 5;
            wbuf[c*257+O] = sw_g[l*8192 + O*32 + c];
        }
        __syncthreads();
#pragma unroll 4
        for(int c = 0; c < 32; c++){
            float w = wbuf[c*257+tid];
            const float4* hp = (const float4*)(hlsT + (l*32+c)*20);
#pragma unroll
            for(int m4 = 0; m4 < 4; m4++){
                float4 h4 = hp[m4];
                a[m4*4+0] += h4.x*w; a[m4*4+1] += h4.y*w;
                a[m4*4+2] += h4.z*w; a[m4*4+3] += h4.w*w;
            }
        }
    }
    __syncthreads();
#pragma unroll
    for(int m = 0; m < 16; m++) skipacc[m*256+tid] = fmaxf(a[m], 0.f);
    __syncthreads();

    const float4* sa = (const float4*)skipacc;
    for(int oo = 0; oo < 2; oo++){
        int o = oo*256 + tid;
        float acc[16];
#pragma unroll
        for(int m = 0; m < 16; m++) acc[m] = 0.f;
        const float4* wr = (const float4*)(w1 + o*256);
        for(int c4 = 0; c4 < 64; c4++){
            float4 w = wr[c4];
#pragma unroll
            for(int m = 0; m < 16; m++){
                float4 s = sa[m*64 + c4];
                acc[m] += w.x*s.x + w.y*s.y + w.z*s.z + w.w*s.w;
            }
        }
        float bb = b1[o];
#pragma unroll
        for(int m = 0; m < 16; m++) y1s[m*512+o] = fmaxf(acc[m] + bb, 0.f);
    }
    __syncthreads();

    for(int idx = tid; idx < 16*24; idx += 256){
        int m = idx/24, o = idx - 24*m;
        float acc = b2[o];
        const float4* wp = (const float4*)(w2 + o*512);
        const float4* yp = (const float4*)(y1s + m*512);
        for(int c4 = 0; c4 < 128; c4++){
            float4 ww = wp[c4], yy = yp[c4];
            acc += ww.x*yy.x + ww.y*yy.y + ww.z*yy.z + ww.w*yy.w;
        }
        out[(n0+m)*24 + o] = acc;
    }
}

// ---------------- host ----------------
static inline size_t conv_smem(int tin, bool enter, bool last){
    return (size_t)(2048 + 2048 + (last ? 0 : 1024) + (enter ? 128 : 0) + NPB*tin*32) * 4;
}

extern "C" void kernel_launch(void* const* d_in, const int* in_sizes, int n_in,
                              void* d_out, int out_size)
{
    const float* inputs  = (const float*)d_in[0];
    const int*   esrc    = (const int*)  d_in[1];
    const int*   edst    = (const int*)  d_in[2];
    const float* enter_w = (const float*)d_in[3];
    const float* enter_b = (const float*)d_in[4];
    const float* filt_w  = (const float*)d_in[5];
    const float* filt_b  = (const float*)d_in[6];
    const float* gate_w  = (const float*)d_in[7];
    const float* gate_b  = (const float*)d_in[8];
    const float* gc_w    = (const float*)d_in[9];
    const float* gc_b    = (const float*)d_in[10];
    const float* skip_w  = (const float*)d_in[11];
    const float* skip_b  = (const float*)d_in[12];
    const float* bn_g    = (const float*)d_in[13];
    const float* bn_b    = (const float*)d_in[14];
    const float* out1_w  = (const float*)d_in[15];
    const float* out1_b  = (const float*)d_in[16];
    const float* out2_w  = (const float*)d_in[17];
    const float* out2_b  = (const float*)d_in[18];
    float* out = (float*)d_out;

    static int head_attr_set = 0;
    if(!head_attr_set){
        cudaFuncSetAttribute(k_head, cudaFuncAttributeMaxDynamicSharedMemorySize, 25632*4);
        head_attr_set = 1;
    }

    float *xA, *xB, *pA, *pB, *hh, *hl;
    cudaGetSymbolAddress((void**)&xA, g_xA);
    cudaGetSymbolAddress((void**)&xB, g_xB);
    cudaGetSymbolAddress((void**)&pA, g_pA);
    cudaGetSymbolAddress((void**)&pB, g_pB);
    cudaGetSymbolAddress((void**)&hh, g_h);
    cudaGetSymbolAddress((void**)&hl, g_hl);

    k_hist<<<(N_EDGES+255)/256, 256>>>(edst);
    k_scan<<<1, 1024>>>();
    k_deg <<<(N_NODES+255)/256, 256>>>();
    k_fill<<<(N_EDGES+255)/256, 256>>>(esrc, edst);

    dim3 cb(32, NPB);
    const int GC = N_NODES/NPB;      // 2500
    const int GP = N_NODES/NPB;      // 2500

    // layer 0 (enter fused)
    k_conv<13,1,true,false><<<GC, cb, conv_smem(13,true,false)>>>(
        inputs, enter_w, enter_b,
        filt_w + 0*2048, filt_b + 0*32, gate_w + 0*2048, gate_b + 0*32,
        gc_w + 0*4096, hl + 0*N_NODES*32, xA);
    k_prop<12><<<GP, 256>>>(hh, pA, gc_w + (0*4+1)*1024);
    k_prop<12><<<GP, 256>>>(pA, pB, gc_w + (0*4+2)*1024);
    k_propfin<12,13><<<GP, 256>>>(pB, gc_w + (0*4+3)*1024, xA, xB,
        gc_b + 0*32, bn_g + 0*32, bn_b + 0*32, 1.f/((float)N_NODES*12.f));

#define LAYER(l, TIN, DD, XIN, XNEW)                                                        \
    {                                                                                       \
        const int t = (TIN) - (DD);                                                         \
        k_conv<TIN, DD, false, false><<<GC, cb, conv_smem(TIN,false,false)>>>(              \
            XIN, 0, 0,                                                                      \
            filt_w + (l)*2048, filt_b + (l)*32, gate_w + (l)*2048, gate_b + (l)*32,         \
            gc_w + (l)*4096, hl + (l)*N_NODES*32, 0);                                       \
        k_prop<(TIN)-(DD)><<<GP, 256>>>(hh, pA, gc_w + ((l)*4+1)*1024);                     \
        k_prop<(TIN)-(DD)><<<GP, 256>>>(pA, pB, gc_w + ((l)*4+2)*1024);                     \
        k_propfin<(TIN)-(DD), TIN><<<GP, 256>>>(pB, gc_w + ((l)*4+3)*1024, XIN, XNEW,       \
            gc_b + (l)*32, bn_g + (l)*32, bn_b + (l)*32, 1.f/((float)N_NODES*(float)t));    \
    }

    LAYER(1, 12, 2, xB, xA)
    LAYER(2, 10, 1, xA, xB)
    LAYER(3,  9, 2, xB, xA)
    LAYER(4,  7, 1, xA, xB)
    LAYER(5,  6, 2, xB, xA)
    LAYER(6,  4, 1, xA, xB)
#undef LAYER

    // layer 7: conv + hl only (graph conv / BN / residual are dead code)
    k_conv<3,2,false,true><<<GC, cb, conv_smem(3,false,true)>>>(
        xB, 0, 0,
        filt_w + 7*2048, filt_b + 7*32, gate_w + 7*2048, gate_b + 7*32,
        gc_w, hl + 7*N_NODES*32, 0);

    k_head<<<N_NODES/16, 256, 25632*4>>>(skip_w, skip_b, out1_w, out1_b, out2_w, out2_b, out);
}

// round 4
// speedup vs baseline: 1.3703x; 1.1747x over previous
#include <cuda_runtime.h>
#include <math.h>

#define N_NODES 20000
#define N_EDGES 320000
#define NPB 8
#define PW 4      // warps (nodes) per prop block

// ---------------- device scratch ----------------
__device__ float  g_xA[N_NODES*13*32];
__device__ float  g_xB[N_NODES*13*32];
__device__ float  g_h [N_NODES*12*32];
__device__ float  g_acc[N_NODES*12*32];
__device__ float  g_pA[N_NODES*12*32];
__device__ float  g_pB[N_NODES*12*32];
__device__ float  g_hl[8*N_NODES*32];
__device__ int    g_rowptr[N_NODES+1];
__device__ int    g_curs[N_NODES];
__device__ int    g_cnt[N_NODES];          // static zero-init; k_deg re-zeroes after use
__device__ float  g_invdeg[N_NODES];
__device__ int    g_col[N_EDGES];
__device__ double g_statsS[32*64];         // 32 shards x (32 sum, 32 sumsq); zeroed in finalize
__device__ float  g_affine[64];            // scale[32], bias[32]
__device__ int    g_done;                  // finalize counter; reset in finalize

// ---------------- setup ----------------
__global__ void k_hist(const int* __restrict__ dst){
    int i = blockIdx.x*256 + threadIdx.x;
    if(i < 64) g_affine[i] = (i < 32) ? 1.f : 0.f;
    if(i < N_EDGES) atomicAdd(&g_cnt[dst[i]], 1);
}

__global__ void k_scan(){
    const int CH = 20;
    int tid = threadIdx.x;
    int b0 = tid*CH; if(b0 > N_NODES) b0 = N_NODES;
    int b1 = b0 + CH; if(b1 > N_NODES) b1 = N_NODES;
    int sum = 0;
    for(int i = b0; i < b1; i++) sum += g_cnt[i];
    int lane = tid & 31, w = tid >> 5;
    int v = sum;
#pragma unroll
    for(int o = 1; o < 32; o <<= 1){
        int t = __shfl_up_sync(0xffffffffu, v, o);
        if(lane >= o) v += t;
    }
    __shared__ int wsum[32];
    if(lane == 31) wsum[w] = v;
    __syncthreads();
    if(w == 0){
        int x = wsum[lane];
#pragma unroll
        for(int o = 1; o < 32; o <<= 1){
            int t = __shfl_up_sync(0xffffffffu, x, o);
            if(lane >= o) x += t;
        }
        wsum[lane] = x;
    }
    __syncthreads();
    int pre = v - sum + ((w > 0) ? wsum[w-1] : 0);
    int run = pre;
    for(int i = b0; i < b1; i++){
        int c = g_cnt[i];
        g_curs[i] = run;
        run += c;
        g_rowptr[i+1] = run;
    }
    if(tid == 0) g_rowptr[0] = 0;
}

__global__ void k_deg(){
    int n = blockIdx.x*256 + threadIdx.x;
    if(n < N_NODES){
        int c = g_cnt[n];
        g_invdeg[n] = 1.f/(float)(c > 0 ? c : 1);
        g_cnt[n] = 0;
    }
}

__global__ void k_fill(const int* __restrict__ src, const int* __restrict__ dst){
    int e = blockIdx.x*256 + threadIdx.x;
    if(e < N_EDGES){
        int pos = atomicAdd(&g_curs[dst[e]], 1);
        g_col[pos] = src[e];
    }
}

// ---------------- gated dilated conv (+enter fusion) + h@W0 + hl ----------------
template<int TIN, int D, bool ENTER, bool LAST>
__global__ void __launch_bounds__(32*NPB) k_conv(
    const float* __restrict__ xin,
    const float* __restrict__ ew, const float* __restrict__ eb,
    const float* __restrict__ fw_g, const float* __restrict__ fb_g,
    const float* __restrict__ gw_g, const float* __restrict__ gb_g,
    const float* __restrict__ w0_g,
    float* __restrict__ hl_out, float* __restrict__ xsave)
{
    constexpr int TOUT = TIN - D;
    extern __shared__ float sm[];
    float* fw  = sm;
    float* gw  = sm + 2048;
    float* w0  = sm + 4096;
    float* ews = sm + 4096 + (LAST ? 0 : 1024);
    float* xs  = ews + (ENTER ? 128 : 0);

    int tx = threadIdx.x, ty = threadIdx.y;
    int tid = ty*32 + tx;
    for(int j = tid; j < 2048; j += 32*NPB){
        int o = j & 31, k = (j>>5) & 1, i = j>>6;
        fw[j] = fw_g[(o*32+i)*2+k];
        gw[j] = gw_g[(o*32+i)*2+k];
    }
    if(!LAST) for(int j = tid; j < 1024; j += 32*NPB) w0[j] = w0_g[j];
    if(ENTER){
        if(tid < 96) ews[tid] = ew[tid];
        if(tid < 32) ews[96+tid] = eb[tid];
    }
    __syncthreads();

    int n = blockIdx.x*NPB + ty;
    float* xrow = xs + ty*(TIN*32);
    if(ENTER){
        const float* ip = xin + n*(TIN*3);
        float we0 = ews[tx*3+0], we1 = ews[tx*3+1], we2 = ews[tx*3+2], be = ews[96+tx];
#pragma unroll
        for(int tt = 0; tt < TIN; tt++){
            float v = be + we0*ip[tt*3+0] + we1*ip[tt*3+1] + we2*ip[tt*3+2];
            xrow[tt*32+tx] = v;
            xsave[(n*TIN+tt)*32+tx] = v;
        }
    } else {
        float scl = g_affine[tx], bia = g_affine[32+tx];
        const float* xp = xin + n*(TIN*32);
        for(int idx = tx; idx < TIN*32; idx += 32)
            xrow[idx] = xp[idx]*scl + bia;
    }
    __syncwarp();

    float f[TOUT], g[TOUT];
    float fb = fb_g[tx], gb = gb_g[tx];
#pragma unroll
    for(int t = 0; t < TOUT; t++){ f[t] = fb; g[t] = gb; }
#pragma unroll
    for(int i = 0; i < 32; i++){
        float wf0 = fw[i*64+tx], wf1 = fw[i*64+32+tx];
        float wg0 = gw[i*64+tx], wg1 = gw[i*64+32+tx];
#pragma unroll
        for(int tt = 0; tt < TIN; tt++){
            float xv = xrow[tt*32+i];
            if(tt < TOUT){ f[tt]   += wf0*xv; g[tt]   += wg0*xv; }
            if(tt >= D)  { f[tt-D] += wf1*xv; g[tt-D] += wg1*xv; }
        }
    }
    __syncwarp();

    if(!LAST){
        float* hrow = xrow;
#pragma unroll
        for(int t = 0; t < TOUT; t++){
            float h = tanhf(f[t]) * (1.f/(1.f + expf(-g[t])));
            hrow[t*32+tx] = h;
            g_h[(n*TOUT+t)*32+tx] = h;
        }
        __syncwarp();
        hl_out[n*32+tx] = hrow[(TOUT-1)*32+tx];

        float w0r[32];
#pragma unroll
        for(int c = 0; c < 32; c++) w0r[c] = w0[c*32+tx];
        float u[TOUT];
#pragma unroll
        for(int t = 0; t < TOUT; t++) u[t] = 0.f;
        const float4* hp4 = (const float4*)hrow;
#pragma unroll
        for(int c4 = 0; c4 < 8; c4++){
#pragma unroll
            for(int t = 0; t < TOUT; t++){
                float4 hh = hp4[t*8+c4];
                u[t] += hh.x*w0r[c4*4+0] + hh.y*w0r[c4*4+1] + hh.z*w0r[c4*4+2] + hh.w*w0r[c4*4+3];
            }
        }
#pragma unroll
        for(int t = 0; t < TOUT; t++) g_acc[(n*TOUT+t)*32+tx] = u[t];
    } else {
        float h = tanhf(f[TOUT-1]) * (1.f/(1.f + expf(-g[TOUT-1])));
        hl_out[n*32+tx] = h;
    }
}

// ---------------- float4 gather core: one warp per node ----------------
// NV = float4 slots per lane; slot v covers float4 index v*32+lane of the row (T*8 float4s).
template<int T>
__device__ __forceinline__ void gather_row(const float4* __restrict__ in4,
                                           int n, int lane, float4* acc)
{
    constexpr int NV = (T*8 + 31)/32;
#pragma unroll
    for(int v = 0; v < NV; v++) acc[v] = make_float4(0.f,0.f,0.f,0.f);
    int beg = g_rowptr[n], end = g_rowptr[n+1];
    int e = beg;
    for(; e + 4 <= end; e += 4){
        int s0 = g_col[e], s1 = g_col[e+1], s2 = g_col[e+2], s3 = g_col[e+3];
        const float4* r0 = in4 + s0*(T*8);
        const float4* r1 = in4 + s1*(T*8);
        const float4* r2 = in4 + s2*(T*8);
        const float4* r3 = in4 + s3*(T*8);
        float4 x0[NV], x1[NV], x2[NV], x3[NV];
#pragma unroll
        for(int v = 0; v < NV; v++){
            int idx = v*32 + lane;
            bool ok = (idx < T*8);
            x0[v] = ok ? r0[idx] : make_float4(0.f,0.f,0.f,0.f);
            x1[v] = ok ? r1[idx] : make_float4(0.f,0.f,0.f,0.f);
            x2[v] = ok ? r2[idx] : make_float4(0.f,0.f,0.f,0.f);
            x3[v] = ok ? r3[idx] : make_float4(0.f,0.f,0.f,0.f);
        }
#pragma unroll
        for(int v = 0; v < NV; v++){
            acc[v].x += (x0[v].x + x1[v].x) + (x2[v].x + x3[v].x);
            acc[v].y += (x0[v].y + x1[v].y) + (x2[v].y + x3[v].y);
            acc[v].z += (x0[v].z + x1[v].z) + (x2[v].z + x3[v].z);
            acc[v].w += (x0[v].w + x1[v].w) + (x2[v].w + x3[v].w);
        }
    }
    for(; e < end; e++){
        int s0 = g_col[e];
        const float4* r0 = in4 + s0*(T*8);
#pragma unroll
        for(int v = 0; v < NV; v++){
            int idx = v*32 + lane;
            if(idx < T*8){
                float4 x = r0[idx];
                acc[v].x += x.x; acc[v].y += x.y; acc[v].z += x.z; acc[v].w += x.w;
            }
        }
    }
    float iv = g_invdeg[n];
#pragma unroll
    for(int v = 0; v < NV; v++){
        acc[v].x *= iv; acc[v].y *= iv; acc[v].z *= iv; acc[v].w *= iv;
    }
}

// ---------------- diffusion hop: cur = A*in ; g_acc += cur @ Wk ----------------
template<int T>
__global__ void __launch_bounds__(32*PW) k_prop(
    const float* __restrict__ in, float* __restrict__ curout,
    const float* __restrict__ Wk)
{
    constexpr int NV = (T*8 + 31)/32;
    __shared__ float Ws[1024];
    __shared__ __align__(16) float smS[PW*12*32];
    int tid = threadIdx.x, lane = tid & 31, wid = tid >> 5;
    for(int j = tid; j < 1024; j += 32*PW) Ws[j] = Wk[j];
    __syncthreads();

    int n = blockIdx.x*PW + wid;
    float4 s4[NV];
    gather_row<T>((const float4*)in, n, lane, s4);

    float4* cp = (float4*)curout + n*(T*8);
    float4* tile4 = (float4*)(smS + wid*(T*32));
#pragma unroll
    for(int v = 0; v < NV; v++){
        int idx = v*32 + lane;
        if(idx < T*8){ cp[idx] = s4[v]; tile4[idx] = s4[v]; }
    }
    __syncwarp();

    float Wreg[32];
#pragma unroll
    for(int c = 0; c < 32; c++) Wreg[c] = Ws[c*32+lane];
    float a[T];
#pragma unroll
    for(int t = 0; t < T; t++) a[t] = 0.f;
    const float4* tp = (const float4*)tile4;
#pragma unroll
    for(int c4 = 0; c4 < 8; c4++){
#pragma unroll
        for(int t = 0; t < T; t++){
            float4 sv = tp[t*8+c4];
            a[t] += sv.x*Wreg[c4*4+0] + sv.y*Wreg[c4*4+1] + sv.z*Wreg[c4*4+2] + sv.w*Wreg[c4*4+3];
        }
    }
    float* ap = g_acc + n*(T*32) + lane;
#pragma unroll
    for(int t = 0; t < T; t++) ap[t*32] += a[t];
}

// ---------------- hop 3 fused with finalize ----------------
template<int T, int TIN>
__global__ void __launch_bounds__(32*PW) k_propfin(
    const float* __restrict__ in, const float* __restrict__ Wk,
    const float* __restrict__ xold, float* __restrict__ xnew,
    const float* __restrict__ gcb,
    const float* __restrict__ bng, const float* __restrict__ bnb, float invCnt)
{
    constexpr int NV = (T*8 + 31)/32;
    __shared__ float Ws[1024];
    __shared__ __align__(16) float smS[PW*12*32];
    __shared__ float rs[32*PW], rq[32*PW];
    __shared__ int isLast;
    int tid = threadIdx.x, lane = tid & 31, wid = tid >> 5;
    for(int j = tid; j < 1024; j += 32*PW) Ws[j] = Wk[j];
    __syncthreads();

    int n = blockIdx.x*PW + wid;
    float4 s4[NV];
    gather_row<T>((const float4*)in, n, lane, s4);

    float4* tile4 = (float4*)(smS + wid*(T*32));
#pragma unroll
    for(int v = 0; v < NV; v++){
        int idx = v*32 + lane;
        if(idx < T*8) tile4[idx] = s4[v];
    }
    __syncwarp();

    float Wreg[32];
#pragma unroll
    for(int c = 0; c < 32; c++) Wreg[c] = Ws[c*32+lane];
    float a[T];
#pragma unroll
    for(int t = 0; t < T; t++) a[t] = 0.f;
    const float4* tp = (const float4*)tile4;
#pragma unroll
    for(int c4 = 0; c4 < 8; c4++){
#pragma unroll
        for(int t = 0; t < T; t++){
            float4 sv = tp[t*8+c4];
            a[t] += sv.x*Wreg[c4*4+0] + sv.y*Wreg[c4*4+1] + sv.z*Wreg[c4*4+2] + sv.w*Wreg[c4*4+3];
        }
    }
    float scl = g_affine[lane], bia = g_affine[32+lane];
    float gb  = gcb[lane];
    const float* ao = g_acc + n*(T*32) + lane;
    const float* xo = xold + (n*TIN + (TIN-T))*32 + lane;
    float* xn = xnew + n*(T*32) + lane;
    float sum = 0.f, sq = 0.f;
#pragma unroll
    for(int t = 0; t < T; t++){
        float v = a[t] + ao[t*32] + gb + xo[t*32]*scl + bia;
        xn[t*32] = v;
        sum += v; sq += v*v;
    }
    rs[tid] = sum; rq[tid] = sq;
    __syncthreads();
    if(tid < 32){
        float ts = 0.f, tq = 0.f;
#pragma unroll
        for(int w = 0; w < PW; w++){ ts += rs[w*32+tid]; tq += rq[w*32+tid]; }
        int sh = (blockIdx.x & 31)*64;
        atomicAdd(&g_statsS[sh+tid],    (double)ts);
        atomicAdd(&g_statsS[sh+32+tid], (double)tq);
    }
    if(tid == 0){
        __threadfence();
        int d = atomicAdd(&g_done, 1);
        isLast = (d == (int)gridDim.x - 1) ? 1 : 0;
    }
    __syncthreads();
    if(isLast){
        __threadfence();
        if(tid < 32){
            double S = 0.0, Q = 0.0;
            for(int k = 0; k < 32; k++){ S += g_statsS[k*64+tid]; Q += g_statsS[k*64+32+tid]; }
            double mu  = S*(double)invCnt;
            double var = Q*(double)invCnt - mu*mu;
            if(var < 0.0) var = 0.0;
            float scale = bng[tid] * rsqrtf((float)var + 1e-5f);
            g_affine[tid]    = scale;
            g_affine[32+tid] = bnb[tid] - (float)mu*scale;
        }
        __syncthreads();
        for(int j = tid; j < 2048; j += 32*PW) g_statsS[j] = 0.0;
        if(tid == 0) g_done = 0;
    }
}

// ---------------- head ----------------
__global__ void __launch_bounds__(256) k_head(
    const float* __restrict__ sw_g, const float* __restrict__ sb_g,
    const float* __restrict__ w1, const float* __restrict__ b1,
    const float* __restrict__ w2, const float* __restrict__ b2,
    float* __restrict__ out)
{
    extern __shared__ float sm[];
    float* hlsT    = sm;            // 5120
    float* skipacc = sm + 5120;     // 4096
    float* wbuf    = sm + 9216;     // 8224
    float* y1s     = sm + 17440;    // 8192
    int tid = threadIdx.x;
    int n0 = blockIdx.x*16;

    for(int j = tid; j < 8*16*32; j += 256){
        int c = j & 31, m = (j>>5) & 15, l = j>>9;
        hlsT[(l*32+c)*20 + m] = g_hl[l*(N_NODES*32) + (n0+m)*32 + c];
    }
    float a[16];
    {
        float bs = 0.f;
        for(int l = 0; l < 8; l++) bs += sb_g[l*256+tid];
#pragma unroll
        for(int m = 0; m < 16; m++) a[m] = bs;
    }
    for(int l = 0; l < 8; l++){
        __syncthreads();
        for(int j = tid; j < 8192; j += 256){
            int c = j & 31, O = j >> 5;
            wbuf[c*257+O] = sw_g[l*8192 + O*32 + c];
        }
        __syncthreads();
#pragma unroll 4
        for(int c = 0; c < 32; c++){
            float w = wbuf[c*257+tid];
            const float4* hp = (const float4*)(hlsT + (l*32+c)*20);
#pragma unroll
            for(int m4 = 0; m4 < 4; m4++){
                float4 h4 = hp[m4];
                a[m4*4+0] += h4.x*w; a[m4*4+1] += h4.y*w;
                a[m4*4+2] += h4.z*w; a[m4*4+3] += h4.w*w;
            }
        }
    }
    __syncthreads();
#pragma unroll
    for(int m = 0; m < 16; m++) skipacc[m*256+tid] = fmaxf(a[m], 0.f);
    __syncthreads();

    const float4* sa = (const float4*)skipacc;
    for(int oo = 0; oo < 2; oo++){
        int o = oo*256 + tid;
        float acc[16];
#pragma unroll
        for(int m = 0; m < 16; m++) acc[m] = 0.f;
        const float4* wr = (const float4*)(w1 + o*256);
        for(int c4 = 0; c4 < 64; c4++){
            float4 w = wr[c4];
#pragma unroll
            for(int m = 0; m < 16; m++){
                float4 s = sa[m*64 + c4];
                acc[m] += w.x*s.x + w.y*s.y + w.z*s.z + w.w*s.w;
            }
        }
        float bb = b1[o];
#pragma unroll
        for(int m = 0; m < 16; m++) y1s[m*512+o] = fmaxf(acc[m] + bb, 0.f);
    }
    __syncthreads();

    for(int idx = tid; idx < 16*24; idx += 256){
        int m = idx/24, o = idx - 24*m;
        float acc = b2[o];
        const float4* wp = (const float4*)(w2 + o*512);
        const float4* yp = (const float4*)(y1s + m*512);
        for(int c4 = 0; c4 < 128; c4++){
            float4 ww = wp[c4], yy = yp[c4];
            acc += ww.x*yy.x + ww.y*yy.y + ww.z*yy.z + ww.w*yy.w;
        }
        out[(n0+m)*24 + o] = acc;
    }
}

// ---------------- host ----------------
static inline size_t conv_smem(int tin, bool enter, bool last){
    return (size_t)(2048 + 2048 + (last ? 0 : 1024) + (enter ? 128 : 0) + NPB*tin*32) * 4;
}

extern "C" void kernel_launch(void* const* d_in, const int* in_sizes, int n_in,
                              void* d_out, int out_size)
{
    const float* inputs  = (const float*)d_in[0];
    const int*   esrc    = (const int*)  d_in[1];
    const int*   edst    = (const int*)  d_in[2];
    const float* enter_w = (const float*)d_in[3];
    const float* enter_b = (const float*)d_in[4];
    const float* filt_w  = (const float*)d_in[5];
    const float* filt_b  = (const float*)d_in[6];
    const float* gate_w  = (const float*)d_in[7];
    const float* gate_b  = (const float*)d_in[8];
    const float* gc_w    = (const float*)d_in[9];
    const float* gc_b    = (const float*)d_in[10];
    const float* skip_w  = (const float*)d_in[11];
    const float* skip_b  = (const float*)d_in[12];
    const float* bn_g    = (const float*)d_in[13];
    const float* bn_b    = (const float*)d_in[14];
    const float* out1_w  = (const float*)d_in[15];
    const float* out1_b  = (const float*)d_in[16];
    const float* out2_w  = (const float*)d_in[17];
    const float* out2_b  = (const float*)d_in[18];
    float* out = (float*)d_out;

    static int head_attr_set = 0;
    if(!head_attr_set){
        cudaFuncSetAttribute(k_head, cudaFuncAttributeMaxDynamicSharedMemorySize, 25632*4);
        head_attr_set = 1;
    }

    float *xA, *xB, *pA, *pB, *hh, *hl;
    cudaGetSymbolAddress((void**)&xA, g_xA);
    cudaGetSymbolAddress((void**)&xB, g_xB);
    cudaGetSymbolAddress((void**)&pA, g_pA);
    cudaGetSymbolAddress((void**)&pB, g_pB);
    cudaGetSymbolAddress((void**)&hh, g_h);
    cudaGetSymbolAddress((void**)&hl, g_hl);

    k_hist<<<(N_EDGES+255)/256, 256>>>(edst);
    k_scan<<<1, 1024>>>();
    k_deg <<<(N_NODES+255)/256, 256>>>();
    k_fill<<<(N_EDGES+255)/256, 256>>>(esrc, edst);

    dim3 cb(32, NPB);
    const int GC = N_NODES/NPB;      // 2500
    const int GP = N_NODES/PW;       // 5000

    // layer 0 (enter fused)
    k_conv<13,1,true,false><<<GC, cb, conv_smem(13,true,false)>>>(
        inputs, enter_w, enter_b,
        filt_w + 0*2048, filt_b + 0*32, gate_w + 0*2048, gate_b + 0*32,
        gc_w + 0*4096, hl + 0*N_NODES*32, xA);
    k_prop<12><<<GP, 32*PW>>>(hh, pA, gc_w + (0*4+1)*1024);
    k_prop<12><<<GP, 32*PW>>>(pA, pB, gc_w + (0*4+2)*1024);
    k_propfin<12,13><<<GP, 32*PW>>>(pB, gc_w + (0*4+3)*1024, xA, xB,
        gc_b + 0*32, bn_g + 0*32, bn_b + 0*32, 1.f/((float)N_NODES*12.f));

#define LAYER(l, TIN, DD, XIN, XNEW)                                                        \
    {                                                                                       \
        const int t = (TIN) - (DD);                                                         \
        k_conv<TIN, DD, false, false><<<GC, cb, conv_smem(TIN,false,false)>>>(              \
            XIN, 0, 0,                                                                      \
            filt_w + (l)*2048, filt_b + (l)*32, gate_w + (l)*2048, gate_b + (l)*32,         \
            gc_w + (l)*4096, hl + (l)*N_NODES*32, 0);                                       \
        k_prop<(TIN)-(DD)><<<GP, 32*PW>>>(hh, pA, gc_w + ((l)*4+1)*1024);                   \
        k_prop<(TIN)-(DD)><<<GP, 32*PW>>>(pA, pB, gc_w + ((l)*4+2)*1024);                   \
        k_propfin<(TIN)-(DD), TIN><<<GP, 32*PW>>>(pB, gc_w + ((l)*4+3)*1024, XIN, XNEW,     \
            gc_b + (l)*32, bn_g + (l)*32, bn_b + (l)*32, 1.f/((float)N_NODES*(float)t));    \
    }

    LAYER(1, 12, 2, xB, xA)
    LAYER(2, 10, 1, xA, xB)
    LAYER(3,  9, 2, xB, xA)
    LAYER(4,  7, 1, xA, xB)
    LAYER(5,  6, 2, xB, xA)
    LAYER(6,  4, 1, xA, xB)
#undef LAYER

    // layer 7: conv + hl only
    k_conv<3,2,false,true><<<GC, cb, conv_smem(3,false,true)>>>(
        xB, 0, 0,
        filt_w + 7*2048, filt_b + 7*32, gate_w + 7*2048, gate_b + 7*32,
        gc_w, hl + 7*N_NODES*32, 0);

    k_head<<<N_NODES/16, 256, 25632*4>>>(skip_w, skip_b, out1_w, out1_b, out2_w, out2_b, out);
}

// round 5
// speedup vs baseline: 1.4620x; 1.0669x over previous
#include <cuda_runtime.h>
#include <cuda_fp16.h>
#include <math.h>

#define N_NODES 20000
#define N_EDGES 320000
#define NPB 8
#define PW 4      // warps (nodes) per prop block

// ---------------- device scratch ----------------
__device__ float  g_xA[N_NODES*13*32];
__device__ float  g_xB[N_NODES*13*32];
__device__ __half g_h [N_NODES*12*32];
__device__ float  g_acc[N_NODES*12*32];
__device__ __half g_pA[N_NODES*12*32];
__device__ __half g_pB[N_NODES*12*32];
__device__ float  g_hl[8*N_NODES*32];
__device__ int    g_rowptr[N_NODES+1];
__device__ int    g_curs[N_NODES];
__device__ int    g_cnt[N_NODES];          // static zero-init; scan re-zeroes after use
__device__ float  g_invdeg[N_NODES];
__device__ int    g_col[N_EDGES];
__device__ double g_statsS[32*64];         // 32 shards x (32 sum, 32 sumsq); zeroed in finalize
__device__ float  g_affine[64];            // scale[32], bias[32]
__device__ int    g_done;                  // finalize counter; reset in finalize

__device__ __forceinline__ __half2 H2(unsigned int u){ return *reinterpret_cast<__half2*>(&u); }
__device__ __forceinline__ unsigned int U2(__half2 h){ return *reinterpret_cast<unsigned int*>(&h); }

// ---------------- setup ----------------
__global__ void k_hist(const int* __restrict__ dst){
    int i = blockIdx.x*256 + threadIdx.x;
    if(i < 64) g_affine[i] = (i < 32) ? 1.f : 0.f;
    if(i < N_EDGES) atomicAdd(&g_cnt[dst[i]], 1);
}

__global__ void k_scan(){           // scan + invdeg + cnt reset (deg merged in)
    const int CH = 20;
    int tid = threadIdx.x;
    int b0 = tid*CH; if(b0 > N_NODES) b0 = N_NODES;
    int b1 = b0 + CH; if(b1 > N_NODES) b1 = N_NODES;
    int sum = 0;
    for(int i = b0; i < b1; i++) sum += g_cnt[i];
    int lane = tid & 31, w = tid >> 5;
    int v = sum;
#pragma unroll
    for(int o = 1; o < 32; o <<= 1){
        int t = __shfl_up_sync(0xffffffffu, v, o);
        if(lane >= o) v += t;
    }
    __shared__ int wsum[32];
    if(lane == 31) wsum[w] = v;
    __syncthreads();
    if(w == 0){
        int x = wsum[lane];
#pragma unroll
        for(int o = 1; o < 32; o <<= 1){
            int t = __shfl_up_sync(0xffffffffu, x, o);
            if(lane >= o) x += t;
        }
        wsum[lane] = x;
    }
    __syncthreads();
    int pre = v - sum + ((w > 0) ? wsum[w-1] : 0);
    int run = pre;
    for(int i = b0; i < b1; i++){
        int c = g_cnt[i];
        g_curs[i] = run;
        run += c;
        g_rowptr[i+1] = run;
        g_invdeg[i] = 1.f/(float)(c > 0 ? c : 1);
        g_cnt[i] = 0;
    }
    if(tid == 0) g_rowptr[0] = 0;
}

__global__ void k_fill(const int* __restrict__ src, const int* __restrict__ dst){
    int e = blockIdx.x*256 + threadIdx.x;
    if(e < N_EDGES){
        int pos = atomicAdd(&g_curs[dst[e]], 1);
        g_col[pos] = src[e];
    }
}

// ---------------- gated dilated conv (+enter fusion) + h@W0 + hl ----------------
template<int TIN, int D, bool ENTER, bool LAST>
__global__ void __launch_bounds__(32*NPB) k_conv(
    const float* __restrict__ xin,
    const float* __restrict__ ew, const float* __restrict__ eb,
    const float* __restrict__ fw_g, const float* __restrict__ fb_g,
    const float* __restrict__ gw_g, const float* __restrict__ gb_g,
    const float* __restrict__ w0_g,
    float* __restrict__ hl_out, float* __restrict__ xsave)
{
    constexpr int TOUT = TIN - D;
    extern __shared__ float sm[];
    float* fw  = sm;
    float* gw  = sm + 2048;
    float* w0  = sm + 4096;
    float* ews = sm + 4096 + (LAST ? 0 : 1024);
    float* xs  = ews + (ENTER ? 128 : 0);

    int tx = threadIdx.x, ty = threadIdx.y;
    int tid = ty*32 + tx;
    for(int j = tid; j < 2048; j += 32*NPB){
        int o = j & 31, k = (j>>5) & 1, i = j>>6;
        fw[j] = fw_g[(o*32+i)*2+k];
        gw[j] = gw_g[(o*32+i)*2+k];
    }
    if(!LAST) for(int j = tid; j < 1024; j += 32*NPB) w0[j] = w0_g[j];
    if(ENTER){
        if(tid < 96) ews[tid] = ew[tid];
        if(tid < 32) ews[96+tid] = eb[tid];
    }
    __syncthreads();

    int n = blockIdx.x*NPB + ty;
    float* xrow = xs + ty*(TIN*32);
    if(ENTER){
        const float* ip = xin + n*(TIN*3);
        float we0 = ews[tx*3+0], we1 = ews[tx*3+1], we2 = ews[tx*3+2], be = ews[96+tx];
#pragma unroll
        for(int tt = 0; tt < TIN; tt++){
            float v = be + we0*ip[tt*3+0] + we1*ip[tt*3+1] + we2*ip[tt*3+2];
            xrow[tt*32+tx] = v;
            xsave[(n*TIN+tt)*32+tx] = v;
        }
    } else {
        float scl = g_affine[tx], bia = g_affine[32+tx];
        const float* xp = xin + n*(TIN*32);
        for(int idx = tx; idx < TIN*32; idx += 32)
            xrow[idx] = xp[idx]*scl + bia;
    }
    __syncwarp();

    float f[TOUT], g[TOUT];
    float fb = fb_g[tx], gb = gb_g[tx];
#pragma unroll
    for(int t = 0; t < TOUT; t++){ f[t] = fb; g[t] = gb; }
#pragma unroll
    for(int i = 0; i < 32; i++){
        float wf0 = fw[i*64+tx], wf1 = fw[i*64+32+tx];
        float wg0 = gw[i*64+tx], wg1 = gw[i*64+32+tx];
#pragma unroll
        for(int tt = 0; tt < TIN; tt++){
            float xv = xrow[tt*32+i];
            if(tt < TOUT){ f[tt]   += wf0*xv; g[tt]   += wg0*xv; }
            if(tt >= D)  { f[tt-D] += wf1*xv; g[tt-D] += wg1*xv; }
        }
    }
    __syncwarp();

    if(!LAST){
        float* hrow = xrow;
#pragma unroll
        for(int t = 0; t < TOUT; t++){
            float h = tanhf(f[t]) * (1.f/(1.f + expf(-g[t])));
            hrow[t*32+tx] = h;
            g_h[(n*TOUT+t)*32+tx] = __float2half_rn(h);
        }
        __syncwarp();
        hl_out[n*32+tx] = hrow[(TOUT-1)*32+tx];

        float w0r[32];
#pragma unroll
        for(int c = 0; c < 32; c++) w0r[c] = w0[c*32+tx];
        float u[TOUT];
#pragma unroll
        for(int t = 0; t < TOUT; t++) u[t] = 0.f;
        const float4* hp4 = (const float4*)hrow;
#pragma unroll
        for(int c4 = 0; c4 < 8; c4++){
#pragma unroll
            for(int t = 0; t < TOUT; t++){
                float4 hh = hp4[t*8+c4];
                u[t] += hh.x*w0r[c4*4+0] + hh.y*w0r[c4*4+1] + hh.z*w0r[c4*4+2] + hh.w*w0r[c4*4+3];
            }
        }
#pragma unroll
        for(int t = 0; t < TOUT; t++) g_acc[(n*TOUT+t)*32+tx] = u[t];
    } else {
        float h = tanhf(f[TOUT-1]) * (1.f/(1.f + expf(-g[TOUT-1])));
        hl_out[n*32+tx] = h;
    }
}

// ---------------- fp16 gather core: one warp per node ----------------
// Row = T*32 halfs = T*4 uint4 (8 halfs each). Slot v = uint4 index v*32+lane.
template<int T>
__device__ __forceinline__ void gather_row_h(const uint4* __restrict__ in,
                                             int n, int lane, float* acc)
{
    constexpr int R  = T*4;
    constexpr int NV = (R + 31)/32;
#pragma unroll
    for(int k = 0; k < NV*8; k++) acc[k] = 0.f;
    int beg = g_rowptr[n], end = g_rowptr[n+1];
    int e = beg;
    for(; e + 4 <= end; e += 4){
        int s0 = g_col[e], s1 = g_col[e+1], s2 = g_col[e+2], s3 = g_col[e+3];
        const uint4* r0 = in + s0*R;
        const uint4* r1 = in + s1*R;
        const uint4* r2 = in + s2*R;
        const uint4* r3 = in + s3*R;
        uint4 q0[NV], q1[NV], q2[NV], q3[NV];
#pragma unroll
        for(int v = 0; v < NV; v++){
            int idx = v*32 + lane;
            if(idx < R){
                q0[v] = r0[idx]; q1[v] = r1[idx]; q2[v] = r2[idx]; q3[v] = r3[idx];
            }
        }
#pragma unroll
        for(int v = 0; v < NV; v++){
            int idx = v*32 + lane;
            if(idx < R){
                __half2 px = __hadd2(__hadd2(H2(q0[v].x), H2(q1[v].x)), __hadd2(H2(q2[v].x), H2(q3[v].x)));
                __half2 py = __hadd2(__hadd2(H2(q0[v].y), H2(q1[v].y)), __hadd2(H2(q2[v].y), H2(q3[v].y)));
                __half2 pz = __hadd2(__hadd2(H2(q0[v].z), H2(q1[v].z)), __hadd2(H2(q2[v].z), H2(q3[v].z)));
                __half2 pw = __hadd2(__hadd2(H2(q0[v].w), H2(q1[v].w)), __hadd2(H2(q2[v].w), H2(q3[v].w)));
                float2 f;
                f = __half22float2(px); acc[v*8+0] += f.x; acc[v*8+1] += f.y;
                f = __half22float2(py); acc[v*8+2] += f.x; acc[v*8+3] += f.y;
                f = __half22float2(pz); acc[v*8+4] += f.x; acc[v*8+5] += f.y;
                f = __half22float2(pw); acc[v*8+6] += f.x; acc[v*8+7] += f.y;
            }
        }
    }
    for(; e < end; e++){
        int s0 = g_col[e];
        const uint4* r0 = in + s0*R;
#pragma unroll
        for(int v = 0; v < NV; v++){
            int idx = v*32 + lane;
            if(idx < R){
                uint4 q = r0[idx];
                float2 f;
                f = __half22float2(H2(q.x)); acc[v*8+0] += f.x; acc[v*8+1] += f.y;
                f = __half22float2(H2(q.y)); acc[v*8+2] += f.x; acc[v*8+3] += f.y;
                f = __half22float2(H2(q.z)); acc[v*8+4] += f.x; acc[v*8+5] += f.y;
                f = __half22float2(H2(q.w)); acc[v*8+6] += f.x; acc[v*8+7] += f.y;
            }
        }
    }
    float iv = g_invdeg[n];
#pragma unroll
    for(int k = 0; k < NV*8; k++) acc[k] *= iv;
}

// scatter gathered values into the fp32 smem tile (t-major, 32 ch)
template<int T>
__device__ __forceinline__ void acc_to_tile(const float* acc, float* tile, int lane){
    constexpr int R  = T*4;
    constexpr int NV = (R + 31)/32;
#pragma unroll
    for(int v = 0; v < NV; v++){
        int idx = v*32 + lane;
        if(idx < R){
            int t = idx >> 2, c0 = (idx & 3) << 3;
            float4* tp = (float4*)(tile + t*32 + c0);
            tp[0] = make_float4(acc[v*8+0], acc[v*8+1], acc[v*8+2], acc[v*8+3]);
            tp[1] = make_float4(acc[v*8+4], acc[v*8+5], acc[v*8+6], acc[v*8+7]);
        }
    }
}

// ---------------- diffusion hop: cur = A*in ; g_acc += cur @ Wk ----------------
template<int T>
__global__ void __launch_bounds__(32*PW) k_prop(
    const __half* __restrict__ in, __half* __restrict__ curout,
    const float* __restrict__ Wk)
{
    constexpr int R  = T*4;
    constexpr int NV = (R + 31)/32;
    __shared__ float Ws[1024];
    __shared__ __align__(16) float smS[PW*12*32];
    int tid = threadIdx.x, lane = tid & 31, wid = tid >> 5;
    for(int j = tid; j < 1024; j += 32*PW) Ws[j] = Wk[j];
    __syncthreads();

    int n = blockIdx.x*PW + wid;
    float acc[NV*8];
    gather_row_h<T>((const uint4*)in, n, lane, acc);

    float* tile = smS + wid*(T*32);
    acc_to_tile<T>(acc, tile, lane);
    uint4* cp = (uint4*)curout + n*R;
#pragma unroll
    for(int v = 0; v < NV; v++){
        int idx = v*32 + lane;
        if(idx < R){
            uint4 q;
            q.x = U2(__floats2half2_rn(acc[v*8+0], acc[v*8+1]));
            q.y = U2(__floats2half2_rn(acc[v*8+2], acc[v*8+3]));
            q.z = U2(__floats2half2_rn(acc[v*8+4], acc[v*8+5]));
            q.w = U2(__floats2half2_rn(acc[v*8+6], acc[v*8+7]));
            cp[idx] = q;
        }
    }
    __syncwarp();

    float Wreg[32];
#pragma unroll
    for(int c = 0; c < 32; c++) Wreg[c] = Ws[c*32+lane];
    float a[T];
#pragma unroll
    for(int t = 0; t < T; t++) a[t] = 0.f;
    const float4* tp = (const float4*)tile;
#pragma unroll
    for(int c4 = 0; c4 < 8; c4++){
#pragma unroll
        for(int t = 0; t < T; t++){
            float4 sv = tp[t*8+c4];
            a[t] += sv.x*Wreg[c4*4+0] + sv.y*Wreg[c4*4+1] + sv.z*Wreg[c4*4+2] + sv.w*Wreg[c4*4+3];
        }
    }
    float* ap = g_acc + n*(T*32) + lane;
#pragma unroll
    for(int t = 0; t < T; t++) ap[t*32] += a[t];
}

// ---------------- hop 3 fused with finalize ----------------
template<int T, int TIN>
__global__ void __launch_bounds__(32*PW) k_propfin(
    const __half* __restrict__ in, const float* __restrict__ Wk,
    const float* __restrict__ xold, float* __restrict__ xnew,
    const float* __restrict__ gcb,
    const float* __restrict__ bng, const float* __restrict__ bnb, float invCnt)
{
    constexpr int R  = T*4;
    constexpr int NV = (R + 31)/32;
    __shared__ float Ws[1024];
    __shared__ __align__(16) float smS[PW*12*32];
    __shared__ float rs[32*PW], rq[32*PW];
    __shared__ int isLast;
    int tid = threadIdx.x, lane = tid & 31, wid = tid >> 5;
    for(int j = tid; j < 1024; j += 32*PW) Ws[j] = Wk[j];
    __syncthreads();

    int n = blockIdx.x*PW + wid;
    float acc[NV*8];
    gather_row_h<T>((const uint4*)in, n, lane, acc);
    float* tile = smS + wid*(T*32);
    acc_to_tile<T>(acc, tile, lane);
    __syncwarp();

    float Wreg[32];
#pragma unroll
    for(int c = 0; c < 32; c++) Wreg[c] = Ws[c*32+lane];
    float a[T];
#pragma unroll
    for(int t = 0; t < T; t++) a[t] = 0.f;
    const float4* tp = (const float4*)tile;
#pragma unroll
    for(int c4 = 0; c4 < 8; c4++){
#pragma unroll
        for(int t = 0; t < T; t++){
            float4 sv = tp[t*8+c4];
            a[t] += sv.x*Wreg[c4*4+0] + sv.y*Wreg[c4*4+1] + sv.z*Wreg[c4*4+2] + sv.w*Wreg[c4*4+3];
        }
    }
    float scl = g_affine[lane], bia = g_affine[32+lane];
    float gb  = gcb[lane];
    const float* ao = g_acc + n*(T*32) + lane;
    const float* xo = xold + (n*TIN + (TIN-T))*32 + lane;
    float* xn = xnew + n*(T*32) + lane;
    float sum = 0.f, sq = 0.f;
#pragma unroll
    for(int t = 0; t < T; t++){
        float v = a[t] + ao[t*32] + gb + xo[t*32]*scl + bia;
        xn[t*32] = v;
        sum += v; sq += v*v;
    }
    rs[tid] = sum; rq[tid] = sq;
    __syncthreads();
    if(tid < 32){
        float ts = 0.f, tq = 0.f;
#pragma unroll
        for(int w = 0; w < PW; w++){ ts += rs[w*32+tid]; tq += rq[w*32+tid]; }
        int sh = (blockIdx.x & 31)*64;
        atomicAdd(&g_statsS[sh+tid],    (double)ts);
        atomicAdd(&g_statsS[sh+32+tid], (double)tq);
    }
    if(tid == 0){
        __threadfence();
        int d = atomicAdd(&g_done, 1);
        isLast = (d == (int)gridDim.x - 1) ? 1 : 0;
    }
    __syncthreads();
    if(isLast){
        __threadfence();
        if(tid < 32){
            double S = 0.0, Q = 0.0;
            for(int k = 0; k < 32; k++){ S += g_statsS[k*64+tid]; Q += g_statsS[k*64+32+tid]; }
            double mu  = S*(double)invCnt;
            double var = Q*(double)invCnt - mu*mu;
            if(var < 0.0) var = 0.0;
            float scale = bng[tid] * rsqrtf((float)var + 1e-5f);
            g_affine[tid]    = scale;
            g_affine[32+tid] = bnb[tid] - (float)mu*scale;
        }
        __syncthreads();
        for(int j = tid; j < 2048; j += 32*PW) g_statsS[j] = 0.0;
        if(tid == 0) g_done = 0;
    }
}

// ---------------- head ----------------
__global__ void __launch_bounds__(256) k_head(
    const float* __restrict__ sw_g, const float* __restrict__ sb_g,
    const float* __restrict__ w1, const float* __restrict__ b1,
    const float* __restrict__ w2, const float* __restrict__ b2,
    float* __restrict__ out)
{
    extern __shared__ float sm[];
    float* hlsT    = sm;            // 5120
    float* skipacc = sm + 5120;     // 4096
    float* wbuf    = sm + 9216;     // 8224
    float* y1s     = sm + 17440;    // 8192
    int tid = threadIdx.x;
    int n0 = blockIdx.x*16;

    for(int j = tid; j < 8*16*32; j += 256){
        int c = j & 31, m = (j>>5) & 15, l = j>>9;
        hlsT[(l*32+c)*20 + m] = g_hl[l*(N_NODES*32) + (n0+m)*32 + c];
    }
    float a[16];
    {
        float bs = 0.f;
        for(int l = 0; l < 8; l++) bs += sb_g[l*256+tid];
#pragma unroll
        for(int m = 0; m < 16; m++) a[m] = bs;
    }
    for(int l = 0; l < 8; l++){
        __syncthreads();
        for(int j = tid; j < 8192; j += 256){
            int c = j & 31, O = j >> 5;
            wbuf[c*257+O] = sw_g[l*8192 + O*32 + c];
        }
        __syncthreads();
#pragma unroll 4
        for(int c = 0; c < 32; c++){
            float w = wbuf[c*257+tid];
            const float4* hp = (const float4*)(hlsT + (l*32+c)*20);
#pragma unroll
            for(int m4 = 0; m4 < 4; m4++){
                float4 h4 = hp[m4];
                a[m4*4+0] += h4.x*w; a[m4*4+1] += h4.y*w;
                a[m4*4+2] += h4.z*w; a[m4*4+3] += h4.w*w;
            }
        }
    }
    __syncthreads();
#pragma unroll
    for(int m = 0; m < 16; m++) skipacc[m*256+tid] = fmaxf(a[m], 0.f);
    __syncthreads();

    const float4* sa = (const float4*)skipacc;
    for(int oo = 0; oo < 2; oo++){
        int o = oo*256 + tid;
        float acc[16];
#pragma unroll
        for(int m = 0; m < 16; m++) acc[m] = 0.f;
        const float4* wr = (const float4*)(w1 + o*256);
        for(int c4 = 0; c4 < 64; c4++){
            float4 w = wr[c4];
#pragma unroll
            for(int m = 0; m < 16; m++){
                float4 s = sa[m*64 + c4];
                acc[m] += w.x*s.x + w.y*s.y + w.z*s.z + w.w*s.w;
            }
        }
        float bb = b1[o];
#pragma unroll
        for(int m = 0; m < 16; m++) y1s[m*512+o] = fmaxf(acc[m] + bb, 0.f);
    }
    __syncthreads();

    for(int idx = tid; idx < 16*24; idx += 256){
        int m = idx/24, o = idx - 24*m;
        float acc = b2[o];
        const float4* wp = (const float4*)(w2 + o*512);
        const float4* yp = (const float4*)(y1s + m*512);
        for(int c4 = 0; c4 < 128; c4++){
            float4 ww = wp[c4], yy = yp[c4];
            acc += ww.x*yy.x + ww.y*yy.y + ww.z*yy.z + ww.w*yy.w;
        }
        out[(n0+m)*24 + o] = acc;
    }
}

// ---------------- host ----------------
static inline size_t conv_smem(int tin, bool enter, bool last){
    return (size_t)(2048 + 2048 + (last ? 0 : 1024) + (enter ? 128 : 0) + NPB*tin*32) * 4;
}

extern "C" void kernel_launch(void* const* d_in, const int* in_sizes, int n_in,
                              void* d_out, int out_size)
{
    const float* inputs  = (const float*)d_in[0];
    const int*   esrc    = (const int*)  d_in[1];
    const int*   edst    = (const int*)  d_in[2];
    const float* enter_w = (const float*)d_in[3];
    const float* enter_b = (const float*)d_in[4];
    const float* filt_w  = (const float*)d_in[5];
    const float* filt_b  = (const float*)d_in[6];
    const float* gate_w  = (const float*)d_in[7];
    const float* gate_b  = (const float*)d_in[8];
    const float* gc_w    = (const float*)d_in[9];
    const float* gc_b    = (const float*)d_in[10];
    const float* skip_w  = (const float*)d_in[11];
    const float* skip_b  = (const float*)d_in[12];
    const float* bn_g    = (const float*)d_in[13];
    const float* bn_b    = (const float*)d_in[14];
    const float* out1_w  = (const float*)d_in[15];
    const float* out1_b  = (const float*)d_in[16];
    const float* out2_w  = (const float*)d_in[17];
    const float* out2_b  = (const float*)d_in[18];
    float* out = (float*)d_out;

    static int head_attr_set = 0;
    if(!head_attr_set){
        cudaFuncSetAttribute(k_head, cudaFuncAttributeMaxDynamicSharedMemorySize, 25632*4);
        head_attr_set = 1;
    }

    float *xA, *xB, *hl;
    __half *pA, *pB, *hh;
    cudaGetSymbolAddress((void**)&xA, g_xA);
    cudaGetSymbolAddress((void**)&xB, g_xB);
    cudaGetSymbolAddress((void**)&pA, g_pA);
    cudaGetSymbolAddress((void**)&pB, g_pB);
    cudaGetSymbolAddress((void**)&hh, g_h);
    cudaGetSymbolAddress((void**)&hl, g_hl);

    k_hist<<<(N_EDGES+255)/256, 256>>>(edst);
    k_scan<<<1, 1024>>>();
    k_fill<<<(N_EDGES+255)/256, 256>>>(esrc, edst);

    dim3 cb(32, NPB);
    const int GC = N_NODES/NPB;      // 2500
    const int GP = N_NODES/PW;       // 5000

    // layer 0 (enter fused)
    k_conv<13,1,true,false><<<GC, cb, conv_smem(13,true,false)>>>(
        inputs, enter_w, enter_b,
        filt_w + 0*2048, filt_b + 0*32, gate_w + 0*2048, gate_b + 0*32,
        gc_w + 0*4096, hl + 0*N_NODES*32, xA);
    k_prop<12><<<GP, 32*PW>>>(hh, pA, gc_w + (0*4+1)*1024);
    k_prop<12><<<GP, 32*PW>>>(pA, pB, gc_w + (0*4+2)*1024);
    k_propfin<12,13><<<GP, 32*PW>>>(pB, gc_w + (0*4+3)*1024, xA, xB,
        gc_b + 0*32, bn_g + 0*32, bn_b + 0*32, 1.f/((float)N_NODES*12.f));

#define LAYER(l, TIN, DD, XIN, XNEW)                                                        \
    {                                                                                       \
        const int t = (TIN) - (DD);                                                         \
        k_conv<TIN, DD, false, false><<<GC, cb, conv_smem(TIN,false,false)>>>(              \
            XIN, 0, 0,                                                                      \
            filt_w + (l)*2048, filt_b + (l)*32, gate_w + (l)*2048, gate_b + (l)*32,         \
            gc_w + (l)*4096, hl + (l)*N_NODES*32, 0);                                       \
        k_prop<(TIN)-(DD)><<<GP, 32*PW>>>(hh, pA, gc_w + ((l)*4+1)*1024);                   \
        k_prop<(TIN)-(DD)><<<GP, 32*PW>>>(pA, pB, gc_w + ((l)*4+2)*1024);                   \
        k_propfin<(TIN)-(DD), TIN><<<GP, 32*PW>>>(pB, gc_w + ((l)*4+3)*1024, XIN, XNEW,     \
            gc_b + (l)*32, bn_g + (l)*32, bn_b + (l)*32, 1.f/((float)N_NODES*(float)t));    \
    }

    LAYER(1, 12, 2, xB, xA)
    LAYER(2, 10, 1, xA, xB)
    LAYER(3,  9, 2, xB, xA)
    LAYER(4,  7, 1, xA, xB)
    LAYER(5,  6, 2, xB, xA)
    LAYER(6,  4, 1, xA, xB)
#undef LAYER

    // layer 7: conv + hl only
    k_conv<3,2,false,true><<<GC, cb, conv_smem(3,false,true)>>>(
        xB, 0, 0,
        filt_w + 7*2048, filt_b + 7*32, gate_w + 7*2048, gate_b + 7*32,
        gc_w, hl + 7*N_NODES*32, 0);

    k_head<<<N_NODES/16, 256, 25632*4>>>(skip_w, skip_b, out1_w, out1_b, out2_w, out2_b, out);
}

// round 6
// speedup vs baseline: 1.4861x; 1.0165x over previous
#include <cuda_runtime.h>
#include <cuda_fp16.h>
#include <math.h>

#define N_NODES 20000
#define N_EDGES 320000
#define NPB 8
#define PW 4      // warps (nodes) per prop block

// ---------------- device scratch ----------------
__device__ float  g_xA[N_NODES*13*32];
__device__ float  g_xB[N_NODES*13*32];
__device__ __half g_h [N_NODES*12*32];
__device__ float  g_acc[N_NODES*12*32];
__device__ __half g_pA[N_NODES*12*32];
__device__ __half g_pB[N_NODES*12*32];
__device__ float  g_hl[8*N_NODES*32];
__device__ int    g_rowptr[N_NODES+1];
__device__ int    g_curs[N_NODES];
__device__ int    g_cnt[N_NODES];          // static zero-init; scan re-zeroes after use
__device__ float  g_invdeg[N_NODES];
__device__ int    g_col[N_EDGES];
__device__ double g_statsS[32*64];         // 32 shards x (32 sum, 32 sumsq); zeroed in finalize
__device__ float  g_affine[64];            // scale[32], bias[32]
__device__ int    g_done;                  // finalize counter; reset in finalize

__device__ __forceinline__ __half2 H2(unsigned int u){ return *reinterpret_cast<__half2*>(&u); }
__device__ __forceinline__ unsigned int U2(__half2 h){ return *reinterpret_cast<unsigned int*>(&h); }

// ---------------- setup ----------------
__global__ void k_hist(const int* __restrict__ dst){
    int i = blockIdx.x*256 + threadIdx.x;
    if(i < 64) g_affine[i] = (i < 32) ? 1.f : 0.f;
    if(i < N_EDGES) atomicAdd(&g_cnt[dst[i]], 1);
}

__global__ void k_scan(){           // scan + invdeg + cnt reset
    const int CH = 20;
    int tid = threadIdx.x;
    int b0 = tid*CH; if(b0 > N_NODES) b0 = N_NODES;
    int b1 = b0 + CH; if(b1 > N_NODES) b1 = N_NODES;
    int sum = 0;
    for(int i = b0; i < b1; i++) sum += g_cnt[i];
    int lane = tid & 31, w = tid >> 5;
    int v = sum;
#pragma unroll
    for(int o = 1; o < 32; o <<= 1){
        int t = __shfl_up_sync(0xffffffffu, v, o);
        if(lane >= o) v += t;
    }
    __shared__ int wsum[32];
    if(lane == 31) wsum[w] = v;
    __syncthreads();
    if(w == 0){
        int x = wsum[lane];
#pragma unroll
        for(int o = 1; o < 32; o <<= 1){
            int t = __shfl_up_sync(0xffffffffu, x, o);
            if(lane >= o) x += t;
        }
        wsum[lane] = x;
    }
    __syncthreads();
    int pre = v - sum + ((w > 0) ? wsum[w-1] : 0);
    int run = pre;
    for(int i = b0; i < b1; i++){
        int c = g_cnt[i];
        g_curs[i] = run;
        run += c;
        g_rowptr[i+1] = run;
        g_invdeg[i] = 1.f/(float)(c > 0 ? c : 1);
        g_cnt[i] = 0;
    }
    if(tid == 0) g_rowptr[0] = 0;
}

__global__ void k_fill(const int* __restrict__ src, const int* __restrict__ dst){
    int e = blockIdx.x*256 + threadIdx.x;
    if(e < N_EDGES){
        int pos = atomicAdd(&g_curs[dst[e]], 1);
        g_col[pos] = src[e];
    }
}

// ---------------- gated dilated conv (+enter fusion) + h@W0 + hl ----------------
// x staged channel-major in smem (stride TP=20) so inner loop uses LDS.128.
template<int TIN, int D, bool ENTER, bool LAST>
__global__ void __launch_bounds__(32*NPB) k_conv(
    const float* __restrict__ xin,
    const float* __restrict__ ew, const float* __restrict__ eb,
    const float* __restrict__ fw_g, const float* __restrict__ fb_g,
    const float* __restrict__ gw_g, const float* __restrict__ gb_g,
    const float* __restrict__ w0_g,
    float* __restrict__ hl_out, float* __restrict__ xsave)
{
    constexpr int TOUT = TIN - D;
    constexpr int NQ   = (TIN + 3)/4;    // float4s per channel row
    constexpr int TP   = 20;             // padded row stride (floats), 16B-aligned, conflict-limited
    extern __shared__ float sm[];
    float* wq  = sm;                                  // packed [i*32+o] float4 {f0,f1,g0,g1} : 4096 floats
    float* w0  = sm + 4096;                           // 1024 (if !LAST)
    float* ews = sm + 4096 + (LAST ? 0 : 1024);       // 128 (if ENTER)
    float* xs  = ews + (ENTER ? 128 : 0);             // NPB*32*TP

    int tx = threadIdx.x, ty = threadIdx.y;
    int tid = ty*32 + tx;
    for(int j = tid; j < 1024; j += 32*NPB){
        int o = j & 31, i = j >> 5;
        float4 v;
        v.x = fw_g[(o*32+i)*2+0];
        v.y = fw_g[(o*32+i)*2+1];
        v.z = gw_g[(o*32+i)*2+0];
        v.w = gw_g[(o*32+i)*2+1];
        ((float4*)wq)[j] = v;
    }
    if(!LAST) for(int j = tid; j < 1024; j += 32*NPB) w0[j] = w0_g[j];
    if(ENTER){
        if(tid < 96) ews[tid] = ew[tid];
        if(tid < 32) ews[96+tid] = eb[tid];
    }
    __syncthreads();

    int n = blockIdx.x*NPB + ty;
    float* xrow = xs + ty*(32*TP);
    if(ENTER){
        const float* ip = xin + n*(TIN*3);
        float we0 = ews[tx*3+0], we1 = ews[tx*3+1], we2 = ews[tx*3+2], be = ews[96+tx];
#pragma unroll
        for(int tt = 0; tt < TIN; tt++){
            float v = be + we0*ip[tt*3+0] + we1*ip[tt*3+1] + we2*ip[tt*3+2];
            xrow[tx*TP+tt] = v;
            xsave[(n*TIN+tt)*32+tx] = v;
        }
    } else {
        float scl = g_affine[tx], bia = g_affine[32+tx];
        const float* xp = xin + n*(TIN*32);
#pragma unroll
        for(int tt = 0; tt < TIN; tt++)
            xrow[tx*TP+tt] = xp[tt*32+tx]*scl + bia;
    }
    __syncwarp();

    float f[TOUT], g[TOUT];
    float fb = fb_g[tx], gb = gb_g[tx];
#pragma unroll
    for(int t = 0; t < TOUT; t++){ f[t] = fb; g[t] = gb; }
#pragma unroll
    for(int i = 0; i < 32; i++){
        float4 w4 = ((const float4*)wq)[i*32+tx];
        const float4* xq = (const float4*)(xrow + i*TP);
        float xv[NQ*4];
#pragma unroll
        for(int q = 0; q < NQ; q++){
            float4 t4 = xq[q];
            xv[q*4+0] = t4.x; xv[q*4+1] = t4.y; xv[q*4+2] = t4.z; xv[q*4+3] = t4.w;
        }
#pragma unroll
        for(int tt = 0; tt < TIN; tt++){
            float x = xv[tt];
            if(tt < TOUT){ f[tt]   += w4.x*x; g[tt]   += w4.z*x; }
            if(tt >= D)  { f[tt-D] += w4.y*x; g[tt-D] += w4.w*x; }
        }
    }
    __syncwarp();                      // all lanes done reading xrow

    if(!LAST){
        float hlast = 0.f;
#pragma unroll
        for(int t = 0; t < TOUT; t++){
            float h = tanhf(f[t]) * (1.f/(1.f + expf(-g[t])));
            xrow[tx*TP+t] = h;                          // h channel-major
            g_h[(n*TOUT+t)*32+tx] = __float2half_rn(h);
            if(t == TOUT-1) hlast = h;
        }
        hl_out[n*32+tx] = hlast;
        __syncwarp();

        float u[TOUT];
#pragma unroll
        for(int t = 0; t < TOUT; t++) u[t] = 0.f;
#pragma unroll
        for(int c = 0; c < 32; c++){
            float w = w0[c*32+tx];
            const float4* hq = (const float4*)(xrow + c*TP);
#pragma unroll
            for(int q = 0; q < NQ; q++){
                if(q*4 < TOUT){
                    float4 hv = hq[q];
                    u[q*4+0] += hv.x*w;
                    if(q*4+1 < TOUT) u[q*4+1] += hv.y*w;
                    if(q*4+2 < TOUT) u[q*4+2] += hv.z*w;
                    if(q*4+3 < TOUT) u[q*4+3] += hv.w*w;
                }
            }
        }
#pragma unroll
        for(int t = 0; t < TOUT; t++) g_acc[(n*TOUT+t)*32+tx] = u[t];
    } else {
        float h = tanhf(f[TOUT-1]) * (1.f/(1.f + expf(-g[TOUT-1])));
        hl_out[n*32+tx] = h;
    }
}

// ---------------- fp16 gather core: one warp per node ----------------
template<int T>
__device__ __forceinline__ void gather_row_h(const uint4* __restrict__ in,
                                             int n, int lane, float* acc)
{
    constexpr int R  = T*4;
    constexpr int NV = (R + 31)/32;
#pragma unroll
    for(int k = 0; k < NV*8; k++) acc[k] = 0.f;
    int beg = g_rowptr[n], end = g_rowptr[n+1];
    int e = beg;
#pragma unroll 2
    for(; e + 4 <= end; e += 4){
        int s0 = g_col[e], s1 = g_col[e+1], s2 = g_col[e+2], s3 = g_col[e+3];
        const uint4* r0 = in + s0*R;
        const uint4* r1 = in + s1*R;
        const uint4* r2 = in + s2*R;
        const uint4* r3 = in + s3*R;
        uint4 q0[NV], q1[NV], q2[NV], q3[NV];
#pragma unroll
        for(int v = 0; v < NV; v++){
            int idx = v*32 + lane;
            if(idx < R){
                q0[v] = r0[idx]; q1[v] = r1[idx]; q2[v] = r2[idx]; q3[v] = r3[idx];
            }
        }
#pragma unroll
        for(int v = 0; v < NV; v++){
            int idx = v*32 + lane;
            if(idx < R){
                __half2 px = __hadd2(__hadd2(H2(q0[v].x), H2(q1[v].x)), __hadd2(H2(q2[v].x), H2(q3[v].x)));
                __half2 py = __hadd2(__hadd2(H2(q0[v].y), H2(q1[v].y)), __hadd2(H2(q2[v].y), H2(q3[v].y)));
                __half2 pz = __hadd2(__hadd2(H2(q0[v].z), H2(q1[v].z)), __hadd2(H2(q2[v].z), H2(q3[v].z)));
                __half2 pw = __hadd2(__hadd2(H2(q0[v].w), H2(q1[v].w)), __hadd2(H2(q2[v].w), H2(q3[v].w)));
                float2 f;
                f = __half22float2(px); acc[v*8+0] += f.x; acc[v*8+1] += f.y;
                f = __half22float2(py); acc[v*8+2] += f.x; acc[v*8+3] += f.y;
                f = __half22float2(pz); acc[v*8+4] += f.x; acc[v*8+5] += f.y;
                f = __half22float2(pw); acc[v*8+6] += f.x; acc[v*8+7] += f.y;
            }
        }
    }
    for(; e < end; e++){
        int s0 = g_col[e];
        const uint4* r0 = in + s0*R;
#pragma unroll
        for(int v = 0; v < NV; v++){
            int idx = v*32 + lane;
            if(idx < R){
                uint4 q = r0[idx];
                float2 f;
                f = __half22float2(H2(q.x)); acc[v*8+0] += f.x; acc[v*8+1] += f.y;
                f = __half22float2(H2(q.y)); acc[v*8+2] += f.x; acc[v*8+3] += f.y;
                f = __half22float2(H2(q.z)); acc[v*8+4] += f.x; acc[v*8+5] += f.y;
                f = __half22float2(H2(q.w)); acc[v*8+6] += f.x; acc[v*8+7] += f.y;
            }
        }
    }
    float iv = g_invdeg[n];
#pragma unroll
    for(int k = 0; k < NV*8; k++) acc[k] *= iv;
}

template<int T>
__device__ __forceinline__ void acc_to_tile(const float* acc, float* tile, int lane){
    constexpr int R  = T*4;
    constexpr int NV = (R + 31)/32;
#pragma unroll
    for(int v = 0; v < NV; v++){
        int idx = v*32 + lane;
        if(idx < R){
            int t = idx >> 2, c0 = (idx & 3) << 3;
            float4* tp = (float4*)(tile + t*32 + c0);
            tp[0] = make_float4(acc[v*8+0], acc[v*8+1], acc[v*8+2], acc[v*8+3]);
            tp[1] = make_float4(acc[v*8+4], acc[v*8+5], acc[v*8+6], acc[v*8+7]);
        }
    }
}

// ---------------- diffusion hop: cur = A*in ; g_acc += cur @ Wk ----------------
template<int T>
__global__ void __launch_bounds__(32*PW) k_prop(
    const __half* __restrict__ in, __half* __restrict__ curout,
    const float* __restrict__ Wk)
{
    constexpr int R  = T*4;
    constexpr int NV = (R + 31)/32;
    __shared__ float Ws[1024];
    __shared__ __align__(16) float smS[PW*12*32];
    int tid = threadIdx.x, lane = tid & 31, wid = tid >> 5;
    for(int j = tid; j < 1024; j += 32*PW) Ws[j] = Wk[j];
    __syncthreads();

    int n = blockIdx.x*PW + wid;
    float acc[NV*8];
    gather_row_h<T>((const uint4*)in, n, lane, acc);

    float* tile = smS + wid*(T*32);
    acc_to_tile<T>(acc, tile, lane);
    uint4* cp = (uint4*)curout + n*R;
#pragma unroll
    for(int v = 0; v < NV; v++){
        int idx = v*32 + lane;
        if(idx < R){
            uint4 q;
            q.x = U2(__floats2half2_rn(acc[v*8+0], acc[v*8+1]));
            q.y = U2(__floats2half2_rn(acc[v*8+2], acc[v*8+3]));
            q.z = U2(__floats2half2_rn(acc[v*8+4], acc[v*8+5]));
            q.w = U2(__floats2half2_rn(acc[v*8+6], acc[v*8+7]));
            cp[idx] = q;
        }
    }
    __syncwarp();

    float Wreg[32];
#pragma unroll
    for(int c = 0; c < 32; c++) Wreg[c] = Ws[c*32+lane];
    float a[T];
#pragma unroll
    for(int t = 0; t < T; t++) a[t] = 0.f;
    const float4* tp = (const float4*)tile;
#pragma unroll
    for(int c4 = 0; c4 < 8; c4++){
#pragma unroll
        for(int t = 0; t < T; t++){
            float4 sv = tp[t*8+c4];
            a[t] += sv.x*Wreg[c4*4+0] + sv.y*Wreg[c4*4+1] + sv.z*Wreg[c4*4+2] + sv.w*Wreg[c4*4+3];
        }
    }
    float* ap = g_acc + n*(T*32) + lane;
#pragma unroll
    for(int t = 0; t < T; t++) ap[t*32] += a[t];
}

// ---------------- hop 3 fused with finalize ----------------
template<int T, int TIN>
__global__ void __launch_bounds__(32*PW) k_propfin(
    const __half* __restrict__ in, const float* __restrict__ Wk,
    const float* __restrict__ xold, float* __restrict__ xnew,
    const float* __restrict__ gcb,
    const float* __restrict__ bng, const float* __restrict__ bnb, float invCnt)
{
    constexpr int R  = T*4;
    constexpr int NV = (R + 31)/32;
    __shared__ float Ws[1024];
    __shared__ __align__(16) float smS[PW*12*32];
    __shared__ float rs[32*PW], rq[32*PW];
    __shared__ int isLast;
    int tid = threadIdx.x, lane = tid & 31, wid = tid >> 5;
    for(int j = tid; j < 1024; j += 32*PW) Ws[j] = Wk[j];
    __syncthreads();

    int n = blockIdx.x*PW + wid;
    float acc[NV*8];
    gather_row_h<T>((const uint4*)in, n, lane, acc);
    float* tile = smS + wid*(T*32);
    acc_to_tile<T>(acc, tile, lane);
    __syncwarp();

    float Wreg[32];
#pragma unroll
    for(int c = 0; c < 32; c++) Wreg[c] = Ws[c*32+lane];
    float a[T];
#pragma unroll
    for(int t = 0; t < T; t++) a[t] = 0.f;
    const float4* tp = (const float4*)tile;
#pragma unroll
    for(int c4 = 0; c4 < 8; c4++){
#pragma unroll
        for(int t = 0; t < T; t++){
            float4 sv = tp[t*8+c4];
            a[t] += sv.x*Wreg[c4*4+0] + sv.y*Wreg[c4*4+1] + sv.z*Wreg[c4*4+2] + sv.w*Wreg[c4*4+3];
        }
    }
    float scl = g_affine[lane], bia = g_affine[32+lane];
    float gb  = gcb[lane];
    const float* ao = g_acc + n*(T*32) + lane;
    const float* xo = xold + (n*TIN + (TIN-T))*32 + lane;
    float* xn = xnew + n*(T*32) + lane;
    float sum = 0.f, sq = 0.f;
#pragma unroll
    for(int t = 0; t < T; t++){
        float v = a[t] + ao[t*32] + gb + xo[t*32]*scl + bia;
        xn[t*32] = v;
        sum += v; sq += v*v;
    }
    rs[tid] = sum; rq[tid] = sq;
    __syncthreads();
    if(tid < 32){
        float ts = 0.f, tq = 0.f;
#pragma unroll
        for(int w = 0; w < PW; w++){ ts += rs[w*32+tid]; tq += rq[w*32+tid]; }
        int sh = (blockIdx.x & 31)*64;
        atomicAdd(&g_statsS[sh+tid],    (double)ts);
        atomicAdd(&g_statsS[sh+32+tid], (double)tq);
    }
    if(tid == 0){
        __threadfence();
        int d = atomicAdd(&g_done, 1);
        isLast = (d == (int)gridDim.x - 1) ? 1 : 0;
    }
    __syncthreads();
    if(isLast){
        __threadfence();
        if(tid < 32){
            double S = 0.0, Q = 0.0;
            for(int k = 0; k < 32; k++){ S += g_statsS[k*64+tid]; Q += g_statsS[k*64+32+tid]; }
            double mu  = S*(double)invCnt;
            double var = Q*(double)invCnt - mu*mu;
            if(var < 0.0) var = 0.0;
            float scale = bng[tid] * rsqrtf((float)var + 1e-5f);
            g_affine[tid]    = scale;
            g_affine[32+tid] = bnb[tid] - (float)mu*scale;
        }
        __syncthreads();
        for(int j = tid; j < 2048; j += 32*PW) g_statsS[j] = 0.0;
        if(tid == 0) g_done = 0;
    }
}

// ---------------- head ----------------
__global__ void __launch_bounds__(256) k_head(
    const float* __restrict__ sw_g, const float* __restrict__ sb_g,
    const float* __restrict__ w1, const float* __restrict__ b1,
    const float* __restrict__ w2, const float* __restrict__ b2,
    float* __restrict__ out)
{
    extern __shared__ float sm[];
    float* hlsT    = sm;            // 5120
    float* skipacc = sm + 5120;     // 4096
    float* wbuf    = sm + 9216;     // 8224
    float* y1s     = sm + 17440;    // 8192
    int tid = threadIdx.x;
    int n0 = blockIdx.x*16;

    for(int j = tid; j < 8*16*32; j += 256){
        int c = j & 31, m = (j>>5) & 15, l = j>>9;
        hlsT[(l*32+c)*20 + m] = g_hl[l*(N_NODES*32) + (n0+m)*32 + c];
    }
    float a[16];
    {
        float bs = 0.f;
        for(int l = 0; l < 8; l++) bs += sb_g[l*256+tid];
#pragma unroll
        for(int m = 0; m < 16; m++) a[m] = bs;
    }
    for(int l = 0; l < 8; l++){
        __syncthreads();
        for(int j = tid; j < 8192; j += 256){
            int c = j & 31, O = j >> 5;
            wbuf[c*257+O] = sw_g[l*8192 + O*32 + c];
        }
        __syncthreads();
#pragma unroll 4
        for(int c = 0; c < 32; c++){
            float w = wbuf[c*257+tid];
            const float4* hp = (const float4*)(hlsT + (l*32+c)*20);
#pragma unroll
            for(int m4 = 0; m4 < 4; m4++){
                float4 h4 = hp[m4];
                a[m4*4+0] += h4.x*w; a[m4*4+1] += h4.y*w;
                a[m4*4+2] += h4.z*w; a[m4*4+3] += h4.w*w;
            }
        }
    }
    __syncthreads();
#pragma unroll
    for(int m = 0; m < 16; m++) skipacc[m*256+tid] = fmaxf(a[m], 0.f);
    __syncthreads();

    const float4* sa = (const float4*)skipacc;
    for(int oo = 0; oo < 2; oo++){
        int o = oo*256 + tid;
        float acc[16];
#pragma unroll
        for(int m = 0; m < 16; m++) acc[m] = 0.f;
        const float4* wr = (const float4*)(w1 + o*256);
        for(int c4 = 0; c4 < 64; c4++){
            float4 w = wr[c4];
#pragma unroll
            for(int m = 0; m < 16; m++){
                float4 s = sa[m*64 + c4];
                acc[m] += w.x*s.x + w.y*s.y + w.z*s.z + w.w*s.w;
            }
        }
        float bb = b1[o];
#pragma unroll
        for(int m = 0; m < 16; m++) y1s[m*512+o] = fmaxf(acc[m] + bb, 0.f);
    }
    __syncthreads();

    for(int idx = tid; idx < 16*24; idx += 256){
        int m = idx/24, o = idx - 24*m;
        float acc = b2[o];
        const float4* wp = (const float4*)(w2 + o*512);
        const float4* yp = (const float4*)(y1s + m*512);
        for(int c4 = 0; c4 < 128; c4++){
            float4 ww = wp[c4], yy = yp[c4];
            acc += ww.x*yy.x + ww.y*yy.y + ww.z*yy.z + ww.w*yy.w;
        }
        out[(n0+m)*24 + o] = acc;
    }
}

// ---------------- host ----------------
static inline size_t conv_smem(bool enter, bool last){
    return (size_t)(4096 + (last ? 0 : 1024) + (enter ? 128 : 0) + NPB*32*20) * 4;
}

extern "C" void kernel_launch(void* const* d_in, const int* in_sizes, int n_in,
                              void* d_out, int out_size)
{
    const float* inputs  = (const float*)d_in[0];
    const int*   esrc    = (const int*)  d_in[1];
    const int*   edst    = (const int*)  d_in[2];
    const float* enter_w = (const float*)d_in[3];
    const float* enter_b = (const float*)d_in[4];
    const float* filt_w  = (const float*)d_in[5];
    const float* filt_b  = (const float*)d_in[6];
    const float* gate_w  = (const float*)d_in[7];
    const float* gate_b  = (const float*)d_in[8];
    const float* gc_w    = (const float*)d_in[9];
    const float* gc_b    = (const float*)d_in[10];
    const float* skip_w  = (const float*)d_in[11];
    const float* skip_b  = (const float*)d_in[12];
    const float* bn_g    = (const float*)d_in[13];
    const float* bn_b    = (const float*)d_in[14];
    const float* out1_w  = (const float*)d_in[15];
    const float* out1_b  = (const float*)d_in[16];
    const float* out2_w  = (const float*)d_in[17];
    const float* out2_b  = (const float*)d_in[18];
    float* out = (float*)d_out;

    static int head_attr_set = 0;
    if(!head_attr_set){
        cudaFuncSetAttribute(k_head, cudaFuncAttributeMaxDynamicSharedMemorySize, 25632*4);
        head_attr_set = 1;
    }

    float *xA, *xB, *hl;
    __half *pA, *pB, *hh;
    cudaGetSymbolAddress((void**)&xA, g_xA);
    cudaGetSymbolAddress((void**)&xB, g_xB);
    cudaGetSymbolAddress((void**)&pA, g_pA);
    cudaGetSymbolAddress((void**)&pB, g_pB);
    cudaGetSymbolAddress((void**)&hh, g_h);
    cudaGetSymbolAddress((void**)&hl, g_hl);

    k_hist<<<(N_EDGES+255)/256, 256>>>(edst);
    k_scan<<<1, 1024>>>();
    k_fill<<<(N_EDGES+255)/256, 256>>>(esrc, edst);

    dim3 cb(32, NPB);
    const int GC = N_NODES/NPB;      // 2500
    const int GP = N_NODES/PW;       // 5000

    // layer 0 (enter fused)
    k_conv<13,1,true,false><<<GC, cb, conv_smem(true,false)>>>(
        inputs, enter_w, enter_b,
        filt_w + 0*2048, filt_b + 0*32, gate_w + 0*2048, gate_b + 0*32,
        gc_w + 0*4096, hl + 0*N_NODES*32, xA);
    k_prop<12><<<GP, 32*PW>>>(hh, pA, gc_w + (0*4+1)*1024);
    k_prop<12><<<GP, 32*PW>>>(pA, pB, gc_w + (0*4+2)*1024);
    k_propfin<12,13><<<GP, 32*PW>>>(pB, gc_w + (0*4+3)*1024, xA, xB,
        gc_b + 0*32, bn_g + 0*32, bn_b + 0*32, 1.f/((float)N_NODES*12.f));

#define LAYER(l, TIN, DD, XIN, XNEW)                                                        \
    {                                                                                       \
        const int t = (TIN) - (DD);                                                         \
        k_conv<TIN, DD, false, false><<<GC, cb, conv_smem(false,false)>>>(                  \
            XIN, 0, 0,                                                                      \
            filt_w + (l)*2048, filt_b + (l)*32, gate_w + (l)*2048, gate_b + (l)*32,         \
            gc_w + (l)*4096, hl + (l)*N_NODES*32, 0);                                       \
        k_prop<(TIN)-(DD)><<<GP, 32*PW>>>(hh, pA, gc_w + ((l)*4+1)*1024);                   \
        k_prop<(TIN)-(DD)><<<GP, 32*PW>>>(pA, pB, gc_w + ((l)*4+2)*1024);                   \
        k_propfin<(TIN)-(DD), TIN><<<GP, 32*PW>>>(pB, gc_w + ((l)*4+3)*1024, XIN, XNEW,     \
            gc_b + (l)*32, bn_g + (l)*32, bn_b + (l)*32, 1.f/((float)N_NODES*(float)t));    \
    }

    LAYER(1, 12, 2, xB, xA)
    LAYER(2, 10, 1, xA, xB)
    LAYER(3,  9, 2, xB, xA)
    LAYER(4,  7, 1, xA, xB)
    LAYER(5,  6, 2, xB, xA)
    LAYER(6,  4, 1, xA, xB)
#undef LAYER

    // layer 7: conv + hl only
    k_conv<3,2,false,true><<<GC, cb, conv_smem(false,true)>>>(
        xB, 0, 0,
        filt_w + 7*2048, filt_b + 7*32, gate_w + 7*2048, gate_b + 7*32,
        gc_w, hl + 7*N_NODES*32, 0);

    k_head<<<N_NODES/16, 256, 25632*4>>>(skip_w, skip_b, out1_w, out1_b, out2_w, out2_b, out);
}